// round 1
// baseline (speedup 1.0000x reference)
#include <cuda_runtime.h>
#include <cuda_bf16.h>
#include <math_constants.h>

// Problem constants
#define BATCH 8
#define TSEQ  2048
#define NHEAD 6
#define HDIM  64
#define CDIM  (NHEAD * HDIM)      // 384
#define C3    (3 * CDIM)          // 1152
#define MROWS (BATCH * TSEQ)      // 16384

// Scratch (device globals; no runtime allocation allowed)
__device__ float g_q[BATCH * NHEAD * TSEQ * HDIM];   // [B,H,T,D]
__device__ float g_k[BATCH * NHEAD * TSEQ * HDIM];
__device__ float g_v[BATCH * NHEAD * TSEQ * HDIM];
__device__ float g_att[MROWS * CDIM];                // [B,T,C]

// ---------------------------------------------------------------------------
// Kernel 1: QKV GEMM  (x[16384,384] @ w_qkv[384,1152]) with head-scatter epilogue
// 64x64 tile, BK=16, 256 threads, 4x4 per thread.
// ---------------------------------------------------------------------------
__global__ __launch_bounds__(256) void qkv_gemm_kernel(
    const float* __restrict__ A, const float* __restrict__ W)
{
    __shared__ float As[16][64];   // transposed A tile: As[k][m]
    __shared__ float Bs[16][64];   // Bs[k][n]

    const int bm = blockIdx.y * 64;
    const int bn = blockIdx.x * 64;
    const int tid = threadIdx.x;

    const int arow = tid >> 2, acol4 = tid & 3;    // A: 64 rows x 4 float4-cols
    const int brow = tid >> 4, bcol4 = tid & 15;   // B: 16 rows x 16 float4-cols
    const int ty = tid >> 4, tx = tid & 15;

    float acc[4][4];
    #pragma unroll
    for (int i = 0; i < 4; i++)
        #pragma unroll
        for (int j = 0; j < 4; j++) acc[i][j] = 0.f;

    for (int k0 = 0; k0 < CDIM; k0 += 16) {
        float4 av = *(const float4*)(A + (size_t)(bm + arow) * CDIM + k0 + acol4 * 4);
        As[acol4 * 4 + 0][arow] = av.x;
        As[acol4 * 4 + 1][arow] = av.y;
        As[acol4 * 4 + 2][arow] = av.z;
        As[acol4 * 4 + 3][arow] = av.w;
        float4 bv = *(const float4*)(W + (size_t)(k0 + brow) * C3 + bn + bcol4 * 4);
        *(float4*)&Bs[brow][bcol4 * 4] = bv;
        __syncthreads();

        #pragma unroll
        for (int kk = 0; kk < 16; kk++) {
            float4 a = *(const float4*)&As[kk][ty * 4];
            float4 b = *(const float4*)&Bs[kk][tx * 4];
            acc[0][0] += a.x * b.x; acc[0][1] += a.x * b.y; acc[0][2] += a.x * b.z; acc[0][3] += a.x * b.w;
            acc[1][0] += a.y * b.x; acc[1][1] += a.y * b.y; acc[1][2] += a.y * b.z; acc[1][3] += a.y * b.w;
            acc[2][0] += a.z * b.x; acc[2][1] += a.z * b.y; acc[2][2] += a.z * b.z; acc[2][3] += a.z * b.w;
            acc[3][0] += a.w * b.x; acc[3][1] += a.w * b.y; acc[3][2] += a.w * b.z; acc[3][3] += a.w * b.w;
        }
        __syncthreads();
    }

    // Epilogue: whole block maps to one of {q,k,v} and one head (bn % 64 == 0, 384 = 6*64)
    const int which = bn / CDIM;
    const int h     = (bn % CDIM) / HDIM;
    float* dst = (which == 0) ? g_q : (which == 1) ? g_k : g_v;

    #pragma unroll
    for (int i = 0; i < 4; i++) {
        const int gm = bm + ty * 4 + i;
        const int b  = gm >> 11;          // / 2048
        const int t  = gm & 2047;
        float4 v = make_float4(acc[i][0], acc[i][1], acc[i][2], acc[i][3]);
        *(float4*)(dst + ((size_t)((b * NHEAD + h) * TSEQ + t) << 6) + tx * 4) = v;
    }
}

// ---------------------------------------------------------------------------
// Kernel 2: causal flash attention.
// grid = (32 q-tiles, 48 bh). block = 64 threads; thread r owns q-row qt*64+r.
// q and o live in registers; K/V 64x64 tiles staged in smem (broadcast reads).
// ---------------------------------------------------------------------------
__global__ __launch_bounds__(64) void flash_attn_kernel()
{
    const int bh  = blockIdx.y;                    // 0..47
    const int qt  = (gridDim.x - 1) - blockIdx.x;  // heavy tiles first
    const int tid = threadIdx.x;                   // 0..63

    const float* __restrict__ Qb = g_q + (size_t)bh * TSEQ * HDIM;
    const float* __restrict__ Kb = g_k + (size_t)bh * TSEQ * HDIM;
    const float* __restrict__ Vb = g_v + (size_t)bh * TSEQ * HDIM;

    const int qi = qt * 64 + tid;

    float4 q[16];
    {
        const float4* qr = (const float4*)(Qb + (size_t)qi * HDIM);
        #pragma unroll
        for (int i = 0; i < 16; i++) q[i] = qr[i];
    }
    float4 o[16];
    #pragma unroll
    for (int i = 0; i < 16; i++) o[i] = make_float4(0.f, 0.f, 0.f, 0.f);

    float m = -CUDART_INF_F;
    float l = 0.f;
    const float scale = 0.125f;   // 64^-0.5

    __shared__ float Ks[64 * 64];
    __shared__ float Vs[64 * 64];

    for (int jt = 0; jt <= qt; jt++) {
        // cooperative tile load: 1024 float4 per tile, 16 per thread
        {
            const float4* Kg = (const float4*)(Kb + (size_t)jt * 64 * HDIM);
            const float4* Vg = (const float4*)(Vb + (size_t)jt * 64 * HDIM);
            float4* Ks4 = (float4*)Ks;
            float4* Vs4 = (float4*)Vs;
            #pragma unroll
            for (int i = 0; i < 16; i++) {
                Ks4[i * 64 + tid] = Kg[i * 64 + tid];
                Vs4[i * 64 + tid] = Vg[i * 64 + tid];
            }
        }
        __syncthreads();

        const int jmax = (jt == qt) ? (tid + 1) : 64;   // causal mask on diagonal tile
        for (int j = 0; j < jmax; j++) {
            const float4* kr = (const float4*)(Ks + j * HDIM);
            float s = 0.f;
            #pragma unroll
            for (int d = 0; d < 16; d++) {
                float4 kv = kr[d];
                s += q[d].x * kv.x + q[d].y * kv.y + q[d].z * kv.z + q[d].w * kv.w;
            }
            s *= scale;
            if (s > m) {
                float corr = __expf(m - s);
                l *= corr;
                #pragma unroll
                for (int d = 0; d < 16; d++) {
                    o[d].x *= corr; o[d].y *= corr; o[d].z *= corr; o[d].w *= corr;
                }
                m = s;
            }
            float p = __expf(s - m);
            l += p;
            const float4* vr = (const float4*)(Vs + j * HDIM);
            #pragma unroll
            for (int d = 0; d < 16; d++) {
                float4 vv = vr[d];
                o[d].x += p * vv.x; o[d].y += p * vv.y; o[d].z += p * vv.z; o[d].w += p * vv.w;
            }
        }
        __syncthreads();
    }

    const float inv = 1.f / l;
    const int b = bh / NHEAD, h = bh % NHEAD;
    float4* dst = (float4*)(g_att + (size_t)(b * TSEQ + qi) * CDIM + h * HDIM);
    #pragma unroll
    for (int i = 0; i < 16; i++) {
        float4 v = o[i];
        v.x *= inv; v.y *= inv; v.z *= inv; v.w *= inv;
        dst[i] = v;
    }
}

// ---------------------------------------------------------------------------
// Kernel 3: output projection  (att[16384,384] @ w_proj[384,384] + b_proj)
// ---------------------------------------------------------------------------
__global__ __launch_bounds__(256) void proj_gemm_kernel(
    const float* __restrict__ W, const float* __restrict__ bias,
    float* __restrict__ out)
{
    __shared__ float As[16][64];
    __shared__ float Bs[16][64];

    const int bm = blockIdx.y * 64;
    const int bn = blockIdx.x * 64;
    const int tid = threadIdx.x;

    const int arow = tid >> 2, acol4 = tid & 3;
    const int brow = tid >> 4, bcol4 = tid & 15;
    const int ty = tid >> 4, tx = tid & 15;

    float acc[4][4];
    #pragma unroll
    for (int i = 0; i < 4; i++)
        #pragma unroll
        for (int j = 0; j < 4; j++) acc[i][j] = 0.f;

    const float* A = g_att;

    for (int k0 = 0; k0 < CDIM; k0 += 16) {
        float4 av = *(const float4*)(A + (size_t)(bm + arow) * CDIM + k0 + acol4 * 4);
        As[acol4 * 4 + 0][arow] = av.x;
        As[acol4 * 4 + 1][arow] = av.y;
        As[acol4 * 4 + 2][arow] = av.z;
        As[acol4 * 4 + 3][arow] = av.w;
        float4 bv = *(const float4*)(W + (size_t)(k0 + brow) * CDIM + bn + bcol4 * 4);
        *(float4*)&Bs[brow][bcol4 * 4] = bv;
        __syncthreads();

        #pragma unroll
        for (int kk = 0; kk < 16; kk++) {
            float4 a = *(const float4*)&As[kk][ty * 4];
            float4 b = *(const float4*)&Bs[kk][tx * 4];
            acc[0][0] += a.x * b.x; acc[0][1] += a.x * b.y; acc[0][2] += a.x * b.z; acc[0][3] += a.x * b.w;
            acc[1][0] += a.y * b.x; acc[1][1] += a.y * b.y; acc[1][2] += a.y * b.z; acc[1][3] += a.y * b.w;
            acc[2][0] += a.z * b.x; acc[2][1] += a.z * b.y; acc[2][2] += a.z * b.z; acc[2][3] += a.z * b.w;
            acc[3][0] += a.w * b.x; acc[3][1] += a.w * b.y; acc[3][2] += a.w * b.z; acc[3][3] += a.w * b.w;
        }
        __syncthreads();
    }

    float4 bb = *(const float4*)(bias + bn + tx * 4);
    #pragma unroll
    for (int i = 0; i < 4; i++) {
        const int gm = bm + ty * 4 + i;
        float4 v = make_float4(acc[i][0] + bb.x, acc[i][1] + bb.y,
                               acc[i][2] + bb.z, acc[i][3] + bb.w);
        *(float4*)(out + (size_t)gm * CDIM + bn + tx * 4) = v;
    }
}

// ---------------------------------------------------------------------------
extern "C" void kernel_launch(void* const* d_in, const int* in_sizes, int n_in,
                              void* d_out, int out_size)
{
    const float* x      = (const float*)d_in[0];   // [8,2048,384]
    const float* w_qkv  = (const float*)d_in[1];   // [384,1152]
    const float* w_proj = (const float*)d_in[2];   // [384,384]
    const float* b_proj = (const float*)d_in[3];   // [384]
    float* out = (float*)d_out;                    // [8,2048,384]

    {
        dim3 grid(C3 / 64, MROWS / 64);            // (18, 256)
        qkv_gemm_kernel<<<grid, 256>>>(x, w_qkv);
    }
    {
        dim3 grid(TSEQ / 64, BATCH * NHEAD);       // (32, 48)
        flash_attn_kernel<<<grid, 64>>>();
    }
    {
        dim3 grid(CDIM / 64, MROWS / 64);          // (6, 256)
        proj_gemm_kernel<<<grid, 256>>>(w_proj, b_proj, out);
    }
}

// round 2
// speedup vs baseline: 2.0193x; 2.0193x over previous
#include <cuda_runtime.h>
#include <cuda_bf16.h>
#include <math_constants.h>

// Problem constants
#define BATCH 8
#define TSEQ  2048
#define NHEAD 6
#define HDIM  64
#define CDIM  (NHEAD * HDIM)      // 384
#define C3    (3 * CDIM)          // 1152
#define MROWS (BATCH * TSEQ)      // 16384

// Scratch (device globals; no runtime allocation allowed)
__device__ float g_q[BATCH * NHEAD * TSEQ * HDIM];   // [B,H,T,D]
__device__ float g_k[BATCH * NHEAD * TSEQ * HDIM];
__device__ float g_v[BATCH * NHEAD * TSEQ * HDIM];
__device__ float g_att[MROWS * CDIM];                // [B,T,C]

// ---------------------------------------------------------------------------
// Kernel 1: QKV GEMM  (x[16384,384] @ w_qkv[384,1152]) with head-scatter epilogue
// ---------------------------------------------------------------------------
__global__ __launch_bounds__(256) void qkv_gemm_kernel(
    const float* __restrict__ A, const float* __restrict__ W)
{
    __shared__ float As[16][64];
    __shared__ float Bs[16][64];

    const int bm = blockIdx.y * 64;
    const int bn = blockIdx.x * 64;
    const int tid = threadIdx.x;

    const int arow = tid >> 2, acol4 = tid & 3;
    const int brow = tid >> 4, bcol4 = tid & 15;
    const int ty = tid >> 4, tx = tid & 15;

    float acc[4][4];
    #pragma unroll
    for (int i = 0; i < 4; i++)
        #pragma unroll
        for (int j = 0; j < 4; j++) acc[i][j] = 0.f;

    for (int k0 = 0; k0 < CDIM; k0 += 16) {
        float4 av = *(const float4*)(A + (size_t)(bm + arow) * CDIM + k0 + acol4 * 4);
        As[acol4 * 4 + 0][arow] = av.x;
        As[acol4 * 4 + 1][arow] = av.y;
        As[acol4 * 4 + 2][arow] = av.z;
        As[acol4 * 4 + 3][arow] = av.w;
        float4 bv = *(const float4*)(W + (size_t)(k0 + brow) * C3 + bn + bcol4 * 4);
        *(float4*)&Bs[brow][bcol4 * 4] = bv;
        __syncthreads();

        #pragma unroll
        for (int kk = 0; kk < 16; kk++) {
            float4 a = *(const float4*)&As[kk][ty * 4];
            float4 b = *(const float4*)&Bs[kk][tx * 4];
            acc[0][0] += a.x * b.x; acc[0][1] += a.x * b.y; acc[0][2] += a.x * b.z; acc[0][3] += a.x * b.w;
            acc[1][0] += a.y * b.x; acc[1][1] += a.y * b.y; acc[1][2] += a.y * b.z; acc[1][3] += a.y * b.w;
            acc[2][0] += a.z * b.x; acc[2][1] += a.z * b.y; acc[2][2] += a.z * b.z; acc[2][3] += a.z * b.w;
            acc[3][0] += a.w * b.x; acc[3][1] += a.w * b.y; acc[3][2] += a.w * b.z; acc[3][3] += a.w * b.w;
        }
        __syncthreads();
    }

    const int which = bn / CDIM;
    const int h     = (bn % CDIM) / HDIM;
    float* dst = (which == 0) ? g_q : (which == 1) ? g_k : g_v;

    #pragma unroll
    for (int i = 0; i < 4; i++) {
        const int gm = bm + ty * 4 + i;
        const int b  = gm >> 11;
        const int t  = gm & 2047;
        float4 v = make_float4(acc[i][0], acc[i][1], acc[i][2], acc[i][3]);
        *(float4*)(dst + ((size_t)((b * NHEAD + h) * TSEQ + t) << 6) + tx * 4) = v;
    }
}

// ---------------------------------------------------------------------------
// Kernel 2: causal flash attention with mma.sync.m16n8k8 tf32.
// grid = (32 q-tiles, 48 bh), block = 128 threads (4 warps).
// Q tile 64 rows; each warp owns 16 rows. K/V/P in swizzled smem.
// ---------------------------------------------------------------------------
__device__ __forceinline__ unsigned f2tf32(float f) {
    unsigned u;
    asm("cvt.rna.tf32.f32 %0, %1;" : "=r"(u) : "f"(f));
    return u;
}
__device__ __forceinline__ float fast_exp2(float x) {
    float y;
    asm("ex2.approx.f32 %0, %1;" : "=f"(y) : "f"(x));
    return y;
}
__device__ __forceinline__ void mma_tf32(float* d, const unsigned* a, unsigned b0, unsigned b1) {
    asm volatile(
        "mma.sync.aligned.m16n8k8.row.col.f32.tf32.tf32.f32 "
        "{%0,%1,%2,%3},{%4,%5,%6,%7},{%8,%9},{%0,%1,%2,%3};"
        : "+f"(d[0]), "+f"(d[1]), "+f"(d[2]), "+f"(d[3])
        : "r"(a[0]), "r"(a[1]), "r"(a[2]), "r"(a[3]), "r"(b0), "r"(b1));
}
// swizzled float index within a 64x64 tile buffer
__device__ __forceinline__ int sw(int row, int col) {
    return row * 64 + (((((unsigned)col >> 2) ^ (row & 7)) << 2) | (col & 3));
}

#define SCALE_LOG2E 0.18033688011112042f   // (1/8) * log2(e)

__global__ __launch_bounds__(128, 3) void flash_attn_kernel()
{
    __shared__ float Ks[64 * 64];
    __shared__ float Vs[64 * 64];
    __shared__ float Ps[64 * 64];

    const int bh   = blockIdx.y;
    const int qt   = (gridDim.x - 1) - blockIdx.x;   // heavy tiles scheduled first
    const int tid  = threadIdx.x;
    const int lane = tid & 31;
    const int warp = tid >> 5;
    const int gid  = lane >> 2;    // group id 0..7
    const int tig  = lane & 3;     // thread in group 0..3

    const float* __restrict__ Qb = g_q + (size_t)bh * TSEQ * HDIM;
    const float* __restrict__ Kb = g_k + (size_t)bh * TSEQ * HDIM;
    const float* __restrict__ Vb = g_v + (size_t)bh * TSEQ * HDIM;

    const int qrow0 = warp * 16 + gid;       // local q row (first half)
    const int qrow1 = qrow0 + 8;             // second half
    const int qg0   = qt * 64 + qrow0;       // global q rows
    const int qg1   = qt * 64 + qrow1;

    // ---- Stage Q tile into Ps, then extract tf32 A fragments ----
    {
        const float4* Qg = (const float4*)(Qb + (size_t)qt * 64 * HDIM);
        float4* P4 = (float4*)Ps;
        #pragma unroll
        for (int i = 0; i < 8; i++) {
            int idx = i * 128 + tid;         // 1024 float4 total
            int row = idx >> 4, c4 = idx & 15;
            P4[row * 16 + (c4 ^ (row & 7))] = Qg[idx];
        }
    }
    __syncthreads();

    unsigned qa[8][4];
    #pragma unroll
    for (int kc = 0; kc < 8; kc++) {
        int col = kc * 8 + tig;
        qa[kc][0] = f2tf32(Ps[sw(qrow0, col)]);
        qa[kc][1] = f2tf32(Ps[sw(qrow1, col)]);
        qa[kc][2] = f2tf32(Ps[sw(qrow0, col + 4)]);
        qa[kc][3] = f2tf32(Ps[sw(qrow1, col + 4)]);
    }
    // (each warp read only its own 16 rows, which it alone will overwrite with P)

    float o[8][4];
    #pragma unroll
    for (int n = 0; n < 8; n++)
        #pragma unroll
        for (int c = 0; c < 4; c++) o[n][c] = 0.f;

    float m0 = -1e30f, m1 = -1e30f, l0 = 0.f, l1 = 0.f;

    for (int jt = 0; jt <= qt; jt++) {
        // ---- cooperative load of K/V tiles (swizzled) ----
        {
            const float4* Kg = (const float4*)(Kb + (size_t)jt * 64 * HDIM);
            const float4* Vg = (const float4*)(Vb + (size_t)jt * 64 * HDIM);
            float4* K4 = (float4*)Ks;
            float4* V4 = (float4*)Vs;
            #pragma unroll
            for (int i = 0; i < 8; i++) {
                int idx = i * 128 + tid;
                int row = idx >> 4, c4 = idx & 15;
                int sidx = row * 16 + (c4 ^ (row & 7));
                K4[sidx] = Kg[idx];
                V4[sidx] = Vg[idx];
            }
        }
        __syncthreads();

        // ---- S = Q K^T (16x64 per warp) ----
        float s[8][4];
        #pragma unroll
        for (int n = 0; n < 8; n++) {
            s[n][0] = s[n][1] = s[n][2] = s[n][3] = 0.f;
            #pragma unroll
            for (int kc = 0; kc < 8; kc++) {
                unsigned b0 = f2tf32(Ks[sw(n * 8 + gid, kc * 8 + tig)]);
                unsigned b1 = f2tf32(Ks[sw(n * 8 + gid, kc * 8 + tig + 4)]);
                mma_tf32(s[n], qa[kc], b0, b1);
            }
        }

        // ---- scale + causal mask ----
        const int jbase = jt * 64;
        const bool diag = (jt == qt);
        #pragma unroll
        for (int n = 0; n < 8; n++) {
            #pragma unroll
            for (int c = 0; c < 4; c++) s[n][c] *= SCALE_LOG2E;
            if (diag) {
                int j0 = jbase + n * 8 + 2 * tig;
                if (j0 > qg0)     s[n][0] = -1e30f;
                if (j0 + 1 > qg0) s[n][1] = -1e30f;
                if (j0 > qg1)     s[n][2] = -1e30f;
                if (j0 + 1 > qg1) s[n][3] = -1e30f;
            }
        }

        // ---- row max (quad reduce) ----
        float mx0 = -1e30f, mx1 = -1e30f;
        #pragma unroll
        for (int n = 0; n < 8; n++) {
            mx0 = fmaxf(mx0, fmaxf(s[n][0], s[n][1]));
            mx1 = fmaxf(mx1, fmaxf(s[n][2], s[n][3]));
        }
        mx0 = fmaxf(mx0, __shfl_xor_sync(0xffffffffu, mx0, 1));
        mx0 = fmaxf(mx0, __shfl_xor_sync(0xffffffffu, mx0, 2));
        mx1 = fmaxf(mx1, __shfl_xor_sync(0xffffffffu, mx1, 1));
        mx1 = fmaxf(mx1, __shfl_xor_sync(0xffffffffu, mx1, 2));

        const float mn0 = fmaxf(m0, mx0);
        const float mn1 = fmaxf(m1, mx1);
        const float cr0 = fast_exp2(m0 - mn0);
        const float cr1 = fast_exp2(m1 - mn1);
        m0 = mn0; m1 = mn1;
        l0 *= cr0; l1 *= cr1;
        #pragma unroll
        for (int n = 0; n < 8; n++) {
            o[n][0] *= cr0; o[n][1] *= cr0;
            o[n][2] *= cr1; o[n][3] *= cr1;
        }

        // ---- p = exp2(s - m), accumulate l, store P to smem ----
        float sum0 = 0.f, sum1 = 0.f;
        #pragma unroll
        for (int n = 0; n < 8; n++) {
            float p00 = fast_exp2(s[n][0] - mn0);
            float p01 = fast_exp2(s[n][1] - mn0);
            float p10 = fast_exp2(s[n][2] - mn1);
            float p11 = fast_exp2(s[n][3] - mn1);
            sum0 += p00 + p01;
            sum1 += p10 + p11;
            int col = n * 8 + 2 * tig;
            *(float2*)&Ps[sw(qrow0, col)] = make_float2(p00, p01);
            *(float2*)&Ps[sw(qrow1, col)] = make_float2(p10, p11);
        }
        sum0 += __shfl_xor_sync(0xffffffffu, sum0, 1);
        sum0 += __shfl_xor_sync(0xffffffffu, sum0, 2);
        sum1 += __shfl_xor_sync(0xffffffffu, sum1, 1);
        sum1 += __shfl_xor_sync(0xffffffffu, sum1, 2);
        l0 += sum0; l1 += sum1;

        __syncwarp();

        // ---- O += P V (16x64 per warp) ----
        #pragma unroll
        for (int kc = 0; kc < 8; kc++) {
            unsigned pa[4];
            int col = kc * 8 + tig;
            pa[0] = f2tf32(Ps[sw(qrow0, col)]);
            pa[1] = f2tf32(Ps[sw(qrow1, col)]);
            pa[2] = f2tf32(Ps[sw(qrow0, col + 4)]);
            pa[3] = f2tf32(Ps[sw(qrow1, col + 4)]);
            #pragma unroll
            for (int dn = 0; dn < 8; dn++) {
                unsigned b0 = f2tf32(Vs[sw(kc * 8 + tig,     dn * 8 + gid)]);
                unsigned b1 = f2tf32(Vs[sw(kc * 8 + tig + 4, dn * 8 + gid)]);
                mma_tf32(o[dn], pa, b0, b1);
            }
        }
        __syncthreads();   // K/V consumption complete before next tile load
    }

    // ---- normalize and write to g_att [B,T,C] ----
    const float inv0 = 1.f / l0;
    const float inv1 = 1.f / l1;
    const int b = bh / NHEAD, h = bh % NHEAD;
    float* base0 = g_att + (size_t)(b * TSEQ + qg0) * CDIM + h * HDIM;
    float* base1 = g_att + (size_t)(b * TSEQ + qg1) * CDIM + h * HDIM;
    #pragma unroll
    for (int dn = 0; dn < 8; dn++) {
        int col = dn * 8 + 2 * tig;
        *(float2*)(base0 + col) = make_float2(o[dn][0] * inv0, o[dn][1] * inv0);
        *(float2*)(base1 + col) = make_float2(o[dn][2] * inv1, o[dn][3] * inv1);
    }
}

// ---------------------------------------------------------------------------
// Kernel 3: output projection  (att[16384,384] @ w_proj[384,384] + b_proj)
// ---------------------------------------------------------------------------
__global__ __launch_bounds__(256) void proj_gemm_kernel(
    const float* __restrict__ W, const float* __restrict__ bias,
    float* __restrict__ out)
{
    __shared__ float As[16][64];
    __shared__ float Bs[16][64];

    const int bm = blockIdx.y * 64;
    const int bn = blockIdx.x * 64;
    const int tid = threadIdx.x;

    const int arow = tid >> 2, acol4 = tid & 3;
    const int brow = tid >> 4, bcol4 = tid & 15;
    const int ty = tid >> 4, tx = tid & 15;

    float acc[4][4];
    #pragma unroll
    for (int i = 0; i < 4; i++)
        #pragma unroll
        for (int j = 0; j < 4; j++) acc[i][j] = 0.f;

    const float* A = g_att;

    for (int k0 = 0; k0 < CDIM; k0 += 16) {
        float4 av = *(const float4*)(A + (size_t)(bm + arow) * CDIM + k0 + acol4 * 4);
        As[acol4 * 4 + 0][arow] = av.x;
        As[acol4 * 4 + 1][arow] = av.y;
        As[acol4 * 4 + 2][arow] = av.z;
        As[acol4 * 4 + 3][arow] = av.w;
        float4 bv = *(const float4*)(W + (size_t)(k0 + brow) * CDIM + bn + bcol4 * 4);
        *(float4*)&Bs[brow][bcol4 * 4] = bv;
        __syncthreads();

        #pragma unroll
        for (int kk = 0; kk < 16; kk++) {
            float4 a = *(const float4*)&As[kk][ty * 4];
            float4 b = *(const float4*)&Bs[kk][tx * 4];
            acc[0][0] += a.x * b.x; acc[0][1] += a.x * b.y; acc[0][2] += a.x * b.z; acc[0][3] += a.x * b.w;
            acc[1][0] += a.y * b.x; acc[1][1] += a.y * b.y; acc[1][2] += a.y * b.z; acc[1][3] += a.y * b.w;
            acc[2][0] += a.z * b.x; acc[2][1] += a.z * b.y; acc[2][2] += a.z * b.z; acc[2][3] += a.z * b.w;
            acc[3][0] += a.w * b.x; acc[3][1] += a.w * b.y; acc[3][2] += a.w * b.z; acc[3][3] += a.w * b.w;
        }
        __syncthreads();
    }

    float4 bb = *(const float4*)(bias + bn + tx * 4);
    #pragma unroll
    for (int i = 0; i < 4; i++) {
        const int gm = bm + ty * 4 + i;
        float4 v = make_float4(acc[i][0] + bb.x, acc[i][1] + bb.y,
                               acc[i][2] + bb.z, acc[i][3] + bb.w);
        *(float4*)(out + (size_t)gm * CDIM + bn + tx * 4) = v;
    }
}

// ---------------------------------------------------------------------------
extern "C" void kernel_launch(void* const* d_in, const int* in_sizes, int n_in,
                              void* d_out, int out_size)
{
    const float* x      = (const float*)d_in[0];
    const float* w_qkv  = (const float*)d_in[1];
    const float* w_proj = (const float*)d_in[2];
    const float* b_proj = (const float*)d_in[3];
    float* out = (float*)d_out;

    {
        dim3 grid(C3 / 64, MROWS / 64);
        qkv_gemm_kernel<<<grid, 256>>>(x, w_qkv);
    }
    {
        dim3 grid(TSEQ / 64, BATCH * NHEAD);
        flash_attn_kernel<<<grid, 128>>>();
    }
    {
        dim3 grid(CDIM / 64, MROWS / 64);
        proj_gemm_kernel<<<grid, 256>>>(w_proj, b_proj, out);
    }
}

// round 4
// speedup vs baseline: 2.1614x; 1.0704x over previous
#include <cuda_runtime.h>
#include <cuda_bf16.h>
#include <math_constants.h>

// Problem constants
#define BATCH 8
#define TSEQ  2048
#define NHEAD 6
#define HDIM  64
#define CDIM  (NHEAD * HDIM)      // 384
#define C3    (3 * CDIM)          // 1152
#define MROWS (BATCH * TSEQ)      // 16384

// Scratch (device globals; no runtime allocation allowed)
__device__ float g_q[BATCH * NHEAD * TSEQ * HDIM];   // [B,H,T,D] (tf32-rounded)
__device__ float g_k[BATCH * NHEAD * TSEQ * HDIM];
__device__ float g_v[BATCH * NHEAD * TSEQ * HDIM];
__device__ float g_att[MROWS * CDIM];                // [B,T,C] fp32

// ---------------------------------------------------------------------------
// Common helpers
// ---------------------------------------------------------------------------
__device__ __forceinline__ unsigned f2tf32(float f) {
    unsigned u;
    asm("cvt.rna.tf32.f32 %0, %1;" : "=r"(u) : "f"(f));
    return u;
}
__device__ __forceinline__ float fast_exp2(float x) {
    float y;
    asm("ex2.approx.f32 %0, %1;" : "=f"(y) : "f"(x));
    return y;
}
__device__ __forceinline__ void mma_tf32(float* d, const unsigned* a, unsigned b0, unsigned b1) {
    asm volatile(
        "mma.sync.aligned.m16n8k8.row.col.f32.tf32.tf32.f32 "
        "{%0,%1,%2,%3},{%4,%5,%6,%7},{%8,%9},{%0,%1,%2,%3};"
        : "+f"(d[0]), "+f"(d[1]), "+f"(d[2]), "+f"(d[3])
        : "r"(a[0]), "r"(a[1]), "r"(a[2]), "r"(a[3]), "r"(b0), "r"(b1));
}
// hi/lo tf32 decomposition of an fp32 value (3xTF32 trick)
__device__ __forceinline__ float2 dec(float x) {
    unsigned hi = f2tf32(x);
    float r = x - __uint_as_float(hi);
    return make_float2(__uint_as_float(hi), __uint_as_float(f2tf32(r)));
}

// ---------------------------------------------------------------------------
// 3xTF32 GEMM: C[M,NC] = A[M,384] @ W[384,NC]  (near-fp32 accuracy)
// BM=BN=128, BK=16, 256 threads = 8 warps (4m x 2n), warp tile 32x64.
// PROJ=false: A = x (arg), scatter into g_q/g_k/g_v with tf32 pre-rounding.
// PROJ=true : A = g_att (device global, resolved IN KERNEL), add bias -> out.
// ---------------------------------------------------------------------------
template<int NC, bool PROJ>
__global__ __launch_bounds__(256, 2) void gemm_tf32_kernel(
    const float* __restrict__ Ain, const float* __restrict__ W,
    const float* __restrict__ bias, float* __restrict__ out)
{
    __shared__ float2 As2[16][128];   // [k][m'] hi/lo pairs, m' = (m + 8*(k&3)) & 127
    __shared__ float2 Bs2[16][128];   // [k][n'] hi/lo pairs, n' = (n + 8*(k&3)) & 127

    // device-side resolution of the device-global scratch (NEVER from host args)
    const float* A = PROJ ? (const float*)g_att : Ain;

    const int tid  = threadIdx.x;
    const int lane = tid & 31, warp = tid >> 5;
    const int wm = warp >> 1, wn = warp & 1;
    const int gid = lane >> 2, tig = lane & 3;
    const int bm = blockIdx.y * 128, bn = blockIdx.x * 128;

    const int arow  = tid >> 1,  acolg = (tid & 1) * 8;
    const int brow  = tid >> 4,  bcolg = (tid & 15) * 8;

    const float* Aptr = A + (size_t)(bm + arow) * CDIM + acolg;
    const float* Wptr = W + (size_t)brow * NC + bn + bcolg;

    float acc[2][8][4];
    #pragma unroll
    for (int mi = 0; mi < 2; mi++)
        #pragma unroll
        for (int ni = 0; ni < 8; ni++)
            #pragma unroll
            for (int c = 0; c < 4; c++) acc[mi][ni][c] = 0.f;

    float4 va0 = *(const float4*)(Aptr);
    float4 va1 = *(const float4*)(Aptr + 4);
    float4 vb0 = *(const float4*)(Wptr);
    float4 vb1 = *(const float4*)(Wptr + 4);

    #pragma unroll 1
    for (int chunk = 0; chunk < 24; chunk++) {
        // ---- decompose & stage ----
        {
            const float* a0 = (const float*)&va0;
            const float* a1 = (const float*)&va1;
            #pragma unroll
            for (int j = 0; j < 4; j++) {
                int msw = (arow + 8 * j) & 127;
                As2[acolg + j][msw]     = dec(a0[j]);
                As2[acolg + 4 + j][msw] = dec(a1[j]);
            }
            int nb = (bcolg + 8 * (brow & 3)) & 127;
            float2 e0 = dec(vb0.x), e1 = dec(vb0.y), e2 = dec(vb0.z), e3 = dec(vb0.w);
            *(float4*)&Bs2[brow][nb]     = make_float4(e0.x, e0.y, e1.x, e1.y);
            *(float4*)&Bs2[brow][nb + 2] = make_float4(e2.x, e2.y, e3.x, e3.y);
            e0 = dec(vb1.x); e1 = dec(vb1.y); e2 = dec(vb1.z); e3 = dec(vb1.w);
            *(float4*)&Bs2[brow][nb + 4] = make_float4(e0.x, e0.y, e1.x, e1.y);
            *(float4*)&Bs2[brow][nb + 6] = make_float4(e2.x, e2.y, e3.x, e3.y);
        }
        // ---- prefetch next chunk ----
        if (chunk < 23) {
            const float* ap = Aptr + (chunk + 1) * 16;
            const float* wp = Wptr + (size_t)(chunk + 1) * 16 * NC;
            va0 = *(const float4*)(ap);
            va1 = *(const float4*)(ap + 4);
            vb0 = *(const float4*)(wp);
            vb1 = *(const float4*)(wp + 4);
        }
        __syncthreads();

        // ---- compute: 2 k-steps of 8 ----
        #pragma unroll
        for (int ks = 0; ks < 2; ks++) {
            const int k0i = ks * 8 + tig;
            const int k1i = k0i + 4;
            const int off = 8 * tig;

            float2 a[2][4];
            #pragma unroll
            for (int mi = 0; mi < 2; mi++) {
                int m  = wm * 32 + mi * 16 + gid;
                int i0 = (m + off) & 127;
                int i1 = (m + 8 + off) & 127;
                a[mi][0] = As2[k0i][i0];
                a[mi][1] = As2[k0i][i1];
                a[mi][2] = As2[k1i][i0];
                a[mi][3] = As2[k1i][i1];
            }
            #pragma unroll
            for (int ni = 0; ni < 8; ni++) {
                int n = (wn * 64 + ni * 8 + gid + off) & 127;
                float2 b0 = Bs2[k0i][n];
                float2 b1 = Bs2[k1i][n];
                #pragma unroll
                for (int mi = 0; mi < 2; mi++) {
                    unsigned ah[4] = {__float_as_uint(a[mi][0].x), __float_as_uint(a[mi][1].x),
                                      __float_as_uint(a[mi][2].x), __float_as_uint(a[mi][3].x)};
                    unsigned al[4] = {__float_as_uint(a[mi][0].y), __float_as_uint(a[mi][1].y),
                                      __float_as_uint(a[mi][2].y), __float_as_uint(a[mi][3].y)};
                    mma_tf32(acc[mi][ni], ah, __float_as_uint(b0.x), __float_as_uint(b1.x));
                    mma_tf32(acc[mi][ni], ah, __float_as_uint(b0.y), __float_as_uint(b1.y));
                    mma_tf32(acc[mi][ni], al, __float_as_uint(b0.x), __float_as_uint(b1.x));
                }
            }
        }
        __syncthreads();
    }

    // ---- epilogue ----
    #pragma unroll
    for (int mi = 0; mi < 2; mi++) {
        const int r0 = bm + wm * 32 + mi * 16 + gid;
        const int r1 = r0 + 8;
        #pragma unroll
        for (int ni = 0; ni < 8; ni++) {
            if (PROJ) {
                const int c = bn + wn * 64 + ni * 8 + tig * 2;
                float bx = bias[c], by = bias[c + 1];
                *(float2*)(out + (size_t)r0 * CDIM + c) =
                    make_float2(acc[mi][ni][0] + bx, acc[mi][ni][1] + by);
                *(float2*)(out + (size_t)r1 * CDIM + c) =
                    make_float2(acc[mi][ni][2] + bx, acc[mi][ni][3] + by);
            } else {
                const int which = bn / CDIM;                       // 0=q,1=k,2=v (no straddle)
                const int cloc  = (bn % CDIM) + wn * 64 + ni * 8 + tig * 2;
                const int h = cloc >> 6, dd = cloc & 63;
                float* dst = (which == 0) ? g_q : (which == 1) ? g_k : g_v;
                const int b0r = r0 >> 11, t0 = r0 & 2047;
                const int b1r = r1 >> 11, t1 = r1 & 2047;
                float2 v0 = make_float2(__uint_as_float(f2tf32(acc[mi][ni][0])),
                                        __uint_as_float(f2tf32(acc[mi][ni][1])));
                float2 v1 = make_float2(__uint_as_float(f2tf32(acc[mi][ni][2])),
                                        __uint_as_float(f2tf32(acc[mi][ni][3])));
                *(float2*)(dst + (((size_t)(b0r * NHEAD + h) * TSEQ + t0) << 6) + dd) = v0;
                *(float2*)(dst + (((size_t)(b1r * NHEAD + h) * TSEQ + t1) << 6) + dd) = v1;
            }
        }
    }
}

// ---------------------------------------------------------------------------
// Causal flash attention with mma.m16n8k8 tf32. q/k/v are pre-rounded to tf32,
// so fragment loads are raw bit loads (no CVT).
// grid = (32 q-tiles, 48 bh), block = 128 threads (4 warps).
// ---------------------------------------------------------------------------
__device__ __forceinline__ int sw(int row, int col) {
    return row * 64 + (((((unsigned)col >> 2) ^ (row & 7)) << 2) | (col & 3));
}

#define SCALE_LOG2E 0.18033688011112042f   // (1/8) * log2(e)

__global__ __launch_bounds__(128, 3) void flash_attn_kernel()
{
    __shared__ float Ks[64 * 64];
    __shared__ float Vs[64 * 64];
    __shared__ float Ps[64 * 64];

    const int bh   = blockIdx.y;
    const int qt   = (gridDim.x - 1) - blockIdx.x;   // heavy tiles first
    const int tid  = threadIdx.x;
    const int lane = tid & 31;
    const int warp = tid >> 5;
    const int gid  = lane >> 2;
    const int tig  = lane & 3;

    const float* __restrict__ Qb = g_q + (size_t)bh * TSEQ * HDIM;
    const float* __restrict__ Kb = g_k + (size_t)bh * TSEQ * HDIM;
    const float* __restrict__ Vb = g_v + (size_t)bh * TSEQ * HDIM;

    const int qrow0 = warp * 16 + gid;
    const int qrow1 = qrow0 + 8;
    const int qg0   = qt * 64 + qrow0;
    const int qg1   = qt * 64 + qrow1;

    // Stage Q tile into Ps (swizzled), then grab fragments (already tf32 bits)
    {
        const float4* Qg = (const float4*)(Qb + (size_t)qt * 64 * HDIM);
        float4* P4 = (float4*)Ps;
        #pragma unroll
        for (int i = 0; i < 8; i++) {
            int idx = i * 128 + tid;
            int row = idx >> 4, c4 = idx & 15;
            P4[row * 16 + (c4 ^ (row & 7))] = Qg[idx];
        }
    }
    __syncthreads();

    unsigned qa[8][4];
    #pragma unroll
    for (int kc = 0; kc < 8; kc++) {
        int col = kc * 8 + tig;
        qa[kc][0] = __float_as_uint(Ps[sw(qrow0, col)]);
        qa[kc][1] = __float_as_uint(Ps[sw(qrow1, col)]);
        qa[kc][2] = __float_as_uint(Ps[sw(qrow0, col + 4)]);
        qa[kc][3] = __float_as_uint(Ps[sw(qrow1, col + 4)]);
    }

    float o[8][4];
    #pragma unroll
    for (int n = 0; n < 8; n++)
        #pragma unroll
        for (int c = 0; c < 4; c++) o[n][c] = 0.f;

    float m0 = -1e30f, m1 = -1e30f, l0 = 0.f, l1 = 0.f;

    for (int jt = 0; jt <= qt; jt++) {
        {
            const float4* Kg = (const float4*)(Kb + (size_t)jt * 64 * HDIM);
            const float4* Vg = (const float4*)(Vb + (size_t)jt * 64 * HDIM);
            float4* K4 = (float4*)Ks;
            float4* V4 = (float4*)Vs;
            #pragma unroll
            for (int i = 0; i < 8; i++) {
                int idx = i * 128 + tid;
                int row = idx >> 4, c4 = idx & 15;
                int sidx = row * 16 + (c4 ^ (row & 7));
                K4[sidx] = Kg[idx];
                V4[sidx] = Vg[idx];
            }
        }
        __syncthreads();

        // S = Q K^T
        float s[8][4];
        #pragma unroll
        for (int n = 0; n < 8; n++) {
            s[n][0] = s[n][1] = s[n][2] = s[n][3] = 0.f;
            #pragma unroll
            for (int kc = 0; kc < 8; kc++) {
                unsigned b0 = __float_as_uint(Ks[sw(n * 8 + gid, kc * 8 + tig)]);
                unsigned b1 = __float_as_uint(Ks[sw(n * 8 + gid, kc * 8 + tig + 4)]);
                mma_tf32(s[n], qa[kc], b0, b1);
            }
        }

        // scale + causal mask
        const int jbase = jt * 64;
        const bool diag = (jt == qt);
        #pragma unroll
        for (int n = 0; n < 8; n++) {
            #pragma unroll
            for (int c = 0; c < 4; c++) s[n][c] *= SCALE_LOG2E;
            if (diag) {
                int j0 = jbase + n * 8 + 2 * tig;
                if (j0 > qg0)     s[n][0] = -1e30f;
                if (j0 + 1 > qg0) s[n][1] = -1e30f;
                if (j0 > qg1)     s[n][2] = -1e30f;
                if (j0 + 1 > qg1) s[n][3] = -1e30f;
            }
        }

        // row max
        float mx0 = -1e30f, mx1 = -1e30f;
        #pragma unroll
        for (int n = 0; n < 8; n++) {
            mx0 = fmaxf(mx0, fmaxf(s[n][0], s[n][1]));
            mx1 = fmaxf(mx1, fmaxf(s[n][2], s[n][3]));
        }
        mx0 = fmaxf(mx0, __shfl_xor_sync(0xffffffffu, mx0, 1));
        mx0 = fmaxf(mx0, __shfl_xor_sync(0xffffffffu, mx0, 2));
        mx1 = fmaxf(mx1, __shfl_xor_sync(0xffffffffu, mx1, 1));
        mx1 = fmaxf(mx1, __shfl_xor_sync(0xffffffffu, mx1, 2));

        const float mn0 = fmaxf(m0, mx0);
        const float mn1 = fmaxf(m1, mx1);
        const float cr0 = fast_exp2(m0 - mn0);
        const float cr1 = fast_exp2(m1 - mn1);
        m0 = mn0; m1 = mn1;
        l0 *= cr0; l1 *= cr1;
        #pragma unroll
        for (int n = 0; n < 8; n++) {
            o[n][0] *= cr0; o[n][1] *= cr0;
            o[n][2] *= cr1; o[n][3] *= cr1;
        }

        // p = exp2(s - m); accumulate l; store P
        float sum0 = 0.f, sum1 = 0.f;
        #pragma unroll
        for (int n = 0; n < 8; n++) {
            float p00 = fast_exp2(s[n][0] - mn0);
            float p01 = fast_exp2(s[n][1] - mn0);
            float p10 = fast_exp2(s[n][2] - mn1);
            float p11 = fast_exp2(s[n][3] - mn1);
            sum0 += p00 + p01;
            sum1 += p10 + p11;
            int col = n * 8 + 2 * tig;
            *(float2*)&Ps[sw(qrow0, col)] = make_float2(p00, p01);
            *(float2*)&Ps[sw(qrow1, col)] = make_float2(p10, p11);
        }
        sum0 += __shfl_xor_sync(0xffffffffu, sum0, 1);
        sum0 += __shfl_xor_sync(0xffffffffu, sum0, 2);
        sum1 += __shfl_xor_sync(0xffffffffu, sum1, 1);
        sum1 += __shfl_xor_sync(0xffffffffu, sum1, 2);
        l0 += sum0; l1 += sum1;

        __syncwarp();

        // O += P V
        #pragma unroll
        for (int kc = 0; kc < 8; kc++) {
            unsigned pa[4];
            int col = kc * 8 + tig;
            pa[0] = f2tf32(Ps[sw(qrow0, col)]);
            pa[1] = f2tf32(Ps[sw(qrow1, col)]);
            pa[2] = f2tf32(Ps[sw(qrow0, col + 4)]);
            pa[3] = f2tf32(Ps[sw(qrow1, col + 4)]);
            #pragma unroll
            for (int dn = 0; dn < 8; dn++) {
                unsigned b0 = __float_as_uint(Vs[sw(kc * 8 + tig,     dn * 8 + gid)]);
                unsigned b1 = __float_as_uint(Vs[sw(kc * 8 + tig + 4, dn * 8 + gid)]);
                mma_tf32(o[dn], pa, b0, b1);
            }
        }
        __syncthreads();
    }

    // normalize + write g_att [B,T,C]
    const float inv0 = 1.f / l0;
    const float inv1 = 1.f / l1;
    const int b = bh / NHEAD, h = bh % NHEAD;
    float* base0 = g_att + (size_t)(b * TSEQ + qg0) * CDIM + h * HDIM;
    float* base1 = g_att + (size_t)(b * TSEQ + qg1) * CDIM + h * HDIM;
    #pragma unroll
    for (int dn = 0; dn < 8; dn++) {
        int col = dn * 8 + 2 * tig;
        *(float2*)(base0 + col) = make_float2(o[dn][0] * inv0, o[dn][1] * inv0);
        *(float2*)(base1 + col) = make_float2(o[dn][2] * inv1, o[dn][3] * inv1);
    }
}

// ---------------------------------------------------------------------------
extern "C" void kernel_launch(void* const* d_in, const int* in_sizes, int n_in,
                              void* d_out, int out_size)
{
    const float* x      = (const float*)d_in[0];   // [8,2048,384]
    const float* w_qkv  = (const float*)d_in[1];   // [384,1152]
    const float* w_proj = (const float*)d_in[2];   // [384,384]
    const float* b_proj = (const float*)d_in[3];   // [384]
    float* out = (float*)d_out;                    // [8,2048,384]

    {
        dim3 grid(C3 / 128, MROWS / 128);          // (9, 128)
        gemm_tf32_kernel<C3, false><<<grid, 256>>>(x, w_qkv, nullptr, nullptr);
    }
    {
        dim3 grid(TSEQ / 64, BATCH * NHEAD);       // (32, 48)
        flash_attn_kernel<<<grid, 128>>>();
    }
    {
        dim3 grid(CDIM / 128, MROWS / 128);        // (3, 128)
        gemm_tf32_kernel<CDIM, true><<<grid, 256>>>(nullptr, w_proj, b_proj, out);
    }
}

// round 5
// speedup vs baseline: 3.1912x; 1.4765x over previous
#include <cuda_runtime.h>
#include <cuda_bf16.h>
#include <math_constants.h>

// Problem constants
#define BATCH 8
#define TSEQ  2048
#define NHEAD 6
#define HDIM  64
#define CDIM  (NHEAD * HDIM)      // 384
#define C3    (3 * CDIM)          // 1152
#define MROWS (BATCH * TSEQ)      // 16384

// Scratch (device globals; no runtime allocation allowed)
__device__ float g_q[BATCH * NHEAD * TSEQ * HDIM];   // [B,H,T,D] (tf32-rounded)
__device__ float g_k[BATCH * NHEAD * TSEQ * HDIM];
__device__ float g_v[BATCH * NHEAD * TSEQ * HDIM];
__device__ float g_att[MROWS * CDIM];                // [B,T,C] fp32

// ---------------------------------------------------------------------------
// Common helpers
// ---------------------------------------------------------------------------
__device__ __forceinline__ unsigned f2tf32(float f) {
    unsigned u;
    asm("cvt.rna.tf32.f32 %0, %1;" : "=r"(u) : "f"(f));
    return u;
}
__device__ __forceinline__ float fast_exp2(float x) {
    float y;
    asm("ex2.approx.f32 %0, %1;" : "=f"(y) : "f"(x));
    return y;
}
__device__ __forceinline__ void mma_tf32(float* d, const unsigned* a, unsigned b0, unsigned b1) {
    asm volatile(
        "mma.sync.aligned.m16n8k8.row.col.f32.tf32.tf32.f32 "
        "{%0,%1,%2,%3},{%4,%5,%6,%7},{%8,%9},{%0,%1,%2,%3};"
        : "+f"(d[0]), "+f"(d[1]), "+f"(d[2]), "+f"(d[3])
        : "r"(a[0]), "r"(a[1]), "r"(a[2]), "r"(a[3]), "r"(b0), "r"(b1));
}

// ---------------------------------------------------------------------------
// Single-pass TF32 GEMM: C[M,NC] = A[M,384] @ W[384,NC]
// BM=BN=128, BK=16, 256 threads = 8 warps (4m x 2n), warp tile 32x64.
// Inputs rounded to tf32 (cvt.rna) at smem staging; fp32 accumulate.
// PROJ=false: A = x (arg), scatter into g_q/g_k/g_v with tf32 pre-rounding.
// PROJ=true : A = g_att (device global, resolved IN KERNEL), add bias -> out.
// smem padded [16][136]: all fragment loads & stages conflict-free/2-way max.
// ---------------------------------------------------------------------------
#define LDP 136

template<int NC, bool PROJ>
__global__ __launch_bounds__(256, 2) void gemm_tf32_kernel(
    const float* __restrict__ Ain, const float* __restrict__ W,
    const float* __restrict__ bias, float* __restrict__ out)
{
    __shared__ float Ash[16][LDP];   // [k][m] tf32 bits
    __shared__ float Bsh[16][LDP];   // [k][n] tf32 bits

    // device-side resolution of the device-global scratch
    const float* A = PROJ ? (const float*)g_att : Ain;

    const int tid  = threadIdx.x;
    const int lane = tid & 31, warp = tid >> 5;
    const int wm = warp >> 1, wn = warp & 1;
    const int gid = lane >> 2, tig = lane & 3;
    const int bm = blockIdx.y * 128, bn = blockIdx.x * 128;

    // A staging: thread -> (row = tid&127, k-group = (tid>>7)*8)
    const int arow  = tid & 127,   acolg = (tid >> 7) * 8;
    // B staging: thread -> (k-row = tid>>4, n-group = (tid&15)*8)
    const int brow  = tid >> 4,    bcolg = (tid & 15) * 8;

    const float* Aptr = A + (size_t)(bm + arow) * CDIM + acolg;
    const float* Wptr = W + (size_t)brow * NC + bn + bcolg;

    float acc[2][8][4];
    #pragma unroll
    for (int mi = 0; mi < 2; mi++)
        #pragma unroll
        for (int ni = 0; ni < 8; ni++)
            #pragma unroll
            for (int c = 0; c < 4; c++) acc[mi][ni][c] = 0.f;

    float4 va0 = *(const float4*)(Aptr);
    float4 va1 = *(const float4*)(Aptr + 4);
    float4 vb0 = *(const float4*)(Wptr);
    float4 vb1 = *(const float4*)(Wptr + 4);

    #pragma unroll 1
    for (int chunk = 0; chunk < 24; chunk++) {
        // ---- stage (tf32-round at store) ----
        {
            const float* a0 = (const float*)&va0;
            const float* a1 = (const float*)&va1;
            #pragma unroll
            for (int j = 0; j < 4; j++) {
                Ash[acolg + j][arow]     = __uint_as_float(f2tf32(a0[j]));
                Ash[acolg + 4 + j][arow] = __uint_as_float(f2tf32(a1[j]));
            }
            float4 r0 = make_float4(__uint_as_float(f2tf32(vb0.x)), __uint_as_float(f2tf32(vb0.y)),
                                    __uint_as_float(f2tf32(vb0.z)), __uint_as_float(f2tf32(vb0.w)));
            float4 r1 = make_float4(__uint_as_float(f2tf32(vb1.x)), __uint_as_float(f2tf32(vb1.y)),
                                    __uint_as_float(f2tf32(vb1.z)), __uint_as_float(f2tf32(vb1.w)));
            *(float4*)&Bsh[brow][bcolg]     = r0;
            *(float4*)&Bsh[brow][bcolg + 4] = r1;
        }
        // ---- prefetch next chunk ----
        if (chunk < 23) {
            const float* ap = Aptr + (chunk + 1) * 16;
            const float* wp = Wptr + (size_t)(chunk + 1) * 16 * NC;
            va0 = *(const float4*)(ap);
            va1 = *(const float4*)(ap + 4);
            vb0 = *(const float4*)(wp);
            vb1 = *(const float4*)(wp + 4);
        }
        __syncthreads();

        // ---- compute: 2 k-steps of 8 ----
        #pragma unroll
        for (int ks = 0; ks < 2; ks++) {
            const int k0i = ks * 8 + tig;
            const int k1i = k0i + 4;

            unsigned a[2][4];
            #pragma unroll
            for (int mi = 0; mi < 2; mi++) {
                const int m = wm * 32 + mi * 16 + gid;
                a[mi][0] = __float_as_uint(Ash[k0i][m]);
                a[mi][1] = __float_as_uint(Ash[k0i][m + 8]);
                a[mi][2] = __float_as_uint(Ash[k1i][m]);
                a[mi][3] = __float_as_uint(Ash[k1i][m + 8]);
            }
            #pragma unroll
            for (int ni = 0; ni < 8; ni++) {
                const int n = wn * 64 + ni * 8 + gid;
                unsigned b0 = __float_as_uint(Bsh[k0i][n]);
                unsigned b1 = __float_as_uint(Bsh[k1i][n]);
                mma_tf32(acc[0][ni], a[0], b0, b1);
                mma_tf32(acc[1][ni], a[1], b0, b1);
            }
        }
        __syncthreads();
    }

    // ---- epilogue ----
    #pragma unroll
    for (int mi = 0; mi < 2; mi++) {
        const int r0 = bm + wm * 32 + mi * 16 + gid;
        const int r1 = r0 + 8;
        #pragma unroll
        for (int ni = 0; ni < 8; ni++) {
            if (PROJ) {
                const int c = bn + wn * 64 + ni * 8 + tig * 2;
                float bx = bias[c], by = bias[c + 1];
                *(float2*)(out + (size_t)r0 * CDIM + c) =
                    make_float2(acc[mi][ni][0] + bx, acc[mi][ni][1] + by);
                *(float2*)(out + (size_t)r1 * CDIM + c) =
                    make_float2(acc[mi][ni][2] + bx, acc[mi][ni][3] + by);
            } else {
                const int which = bn / CDIM;                       // 0=q,1=k,2=v (no straddle)
                const int cloc  = (bn % CDIM) + wn * 64 + ni * 8 + tig * 2;
                const int h = cloc >> 6, dd = cloc & 63;
                float* dst = (which == 0) ? g_q : (which == 1) ? g_k : g_v;
                const int b0r = r0 >> 11, t0 = r0 & 2047;
                const int b1r = r1 >> 11, t1 = r1 & 2047;
                float2 v0 = make_float2(__uint_as_float(f2tf32(acc[mi][ni][0])),
                                        __uint_as_float(f2tf32(acc[mi][ni][1])));
                float2 v1 = make_float2(__uint_as_float(f2tf32(acc[mi][ni][2])),
                                        __uint_as_float(f2tf32(acc[mi][ni][3])));
                *(float2*)(dst + (((size_t)(b0r * NHEAD + h) * TSEQ + t0) << 6) + dd) = v0;
                *(float2*)(dst + (((size_t)(b1r * NHEAD + h) * TSEQ + t1) << 6) + dd) = v1;
            }
        }
    }
}

// ---------------------------------------------------------------------------
// Causal flash attention with mma.m16n8k8 tf32. q/k/v are pre-rounded to tf32,
// so fragment loads are raw bit loads (no CVT).
// grid = (32 q-tiles, 48 bh), block = 128 threads (4 warps).
// ---------------------------------------------------------------------------
__device__ __forceinline__ int sw(int row, int col) {
    return row * 64 + (((((unsigned)col >> 2) ^ (row & 7)) << 2) | (col & 3));
}

#define SCALE_LOG2E 0.18033688011112042f   // (1/8) * log2(e)

__global__ __launch_bounds__(128, 3) void flash_attn_kernel()
{
    __shared__ float Ks[64 * 64];
    __shared__ float Vs[64 * 64];
    __shared__ float Ps[64 * 64];

    const int bh   = blockIdx.y;
    const int qt   = (gridDim.x - 1) - blockIdx.x;   // heavy tiles first
    const int tid  = threadIdx.x;
    const int lane = tid & 31;
    const int warp = tid >> 5;
    const int gid  = lane >> 2;
    const int tig  = lane & 3;

    const float* __restrict__ Qb = g_q + (size_t)bh * TSEQ * HDIM;
    const float* __restrict__ Kb = g_k + (size_t)bh * TSEQ * HDIM;
    const float* __restrict__ Vb = g_v + (size_t)bh * TSEQ * HDIM;

    const int qrow0 = warp * 16 + gid;
    const int qrow1 = qrow0 + 8;
    const int qg0   = qt * 64 + qrow0;
    const int qg1   = qt * 64 + qrow1;

    // Stage Q tile into Ps (swizzled), then grab fragments (already tf32 bits)
    {
        const float4* Qg = (const float4*)(Qb + (size_t)qt * 64 * HDIM);
        float4* P4 = (float4*)Ps;
        #pragma unroll
        for (int i = 0; i < 8; i++) {
            int idx = i * 128 + tid;
            int row = idx >> 4, c4 = idx & 15;
            P4[row * 16 + (c4 ^ (row & 7))] = Qg[idx];
        }
    }
    __syncthreads();

    unsigned qa[8][4];
    #pragma unroll
    for (int kc = 0; kc < 8; kc++) {
        int col = kc * 8 + tig;
        qa[kc][0] = __float_as_uint(Ps[sw(qrow0, col)]);
        qa[kc][1] = __float_as_uint(Ps[sw(qrow1, col)]);
        qa[kc][2] = __float_as_uint(Ps[sw(qrow0, col + 4)]);
        qa[kc][3] = __float_as_uint(Ps[sw(qrow1, col + 4)]);
    }

    float o[8][4];
    #pragma unroll
    for (int n = 0; n < 8; n++)
        #pragma unroll
        for (int c = 0; c < 4; c++) o[n][c] = 0.f;

    float m0 = -1e30f, m1 = -1e30f, l0 = 0.f, l1 = 0.f;

    for (int jt = 0; jt <= qt; jt++) {
        {
            const float4* Kg = (const float4*)(Kb + (size_t)jt * 64 * HDIM);
            const float4* Vg = (const float4*)(Vb + (size_t)jt * 64 * HDIM);
            float4* K4 = (float4*)Ks;
            float4* V4 = (float4*)Vs;
            #pragma unroll
            for (int i = 0; i < 8; i++) {
                int idx = i * 128 + tid;
                int row = idx >> 4, c4 = idx & 15;
                int sidx = row * 16 + (c4 ^ (row & 7));
                K4[sidx] = Kg[idx];
                V4[sidx] = Vg[idx];
            }
        }
        __syncthreads();

        // S = Q K^T
        float s[8][4];
        #pragma unroll
        for (int n = 0; n < 8; n++) {
            s[n][0] = s[n][1] = s[n][2] = s[n][3] = 0.f;
            #pragma unroll
            for (int kc = 0; kc < 8; kc++) {
                unsigned b0 = __float_as_uint(Ks[sw(n * 8 + gid, kc * 8 + tig)]);
                unsigned b1 = __float_as_uint(Ks[sw(n * 8 + gid, kc * 8 + tig + 4)]);
                mma_tf32(s[n], qa[kc], b0, b1);
            }
        }

        // scale + causal mask
        const int jbase = jt * 64;
        const bool diag = (jt == qt);
        #pragma unroll
        for (int n = 0; n < 8; n++) {
            #pragma unroll
            for (int c = 0; c < 4; c++) s[n][c] *= SCALE_LOG2E;
            if (diag) {
                int j0 = jbase + n * 8 + 2 * tig;
                if (j0 > qg0)     s[n][0] = -1e30f;
                if (j0 + 1 > qg0) s[n][1] = -1e30f;
                if (j0 > qg1)     s[n][2] = -1e30f;
                if (j0 + 1 > qg1) s[n][3] = -1e30f;
            }
        }

        // row max
        float mx0 = -1e30f, mx1 = -1e30f;
        #pragma unroll
        for (int n = 0; n < 8; n++) {
            mx0 = fmaxf(mx0, fmaxf(s[n][0], s[n][1]));
            mx1 = fmaxf(mx1, fmaxf(s[n][2], s[n][3]));
        }
        mx0 = fmaxf(mx0, __shfl_xor_sync(0xffffffffu, mx0, 1));
        mx0 = fmaxf(mx0, __shfl_xor_sync(0xffffffffu, mx0, 2));
        mx1 = fmaxf(mx1, __shfl_xor_sync(0xffffffffu, mx1, 1));
        mx1 = fmaxf(mx1, __shfl_xor_sync(0xffffffffu, mx1, 2));

        const float mn0 = fmaxf(m0, mx0);
        const float mn1 = fmaxf(m1, mx1);
        const float cr0 = fast_exp2(m0 - mn0);
        const float cr1 = fast_exp2(m1 - mn1);
        m0 = mn0; m1 = mn1;
        l0 *= cr0; l1 *= cr1;
        #pragma unroll
        for (int n = 0; n < 8; n++) {
            o[n][0] *= cr0; o[n][1] *= cr0;
            o[n][2] *= cr1; o[n][3] *= cr1;
        }

        // p = exp2(s - m); accumulate l; store P
        float sum0 = 0.f, sum1 = 0.f;
        #pragma unroll
        for (int n = 0; n < 8; n++) {
            float p00 = fast_exp2(s[n][0] - mn0);
            float p01 = fast_exp2(s[n][1] - mn0);
            float p10 = fast_exp2(s[n][2] - mn1);
            float p11 = fast_exp2(s[n][3] - mn1);
            sum0 += p00 + p01;
            sum1 += p10 + p11;
            int col = n * 8 + 2 * tig;
            *(float2*)&Ps[sw(qrow0, col)] = make_float2(p00, p01);
            *(float2*)&Ps[sw(qrow1, col)] = make_float2(p10, p11);
        }
        sum0 += __shfl_xor_sync(0xffffffffu, sum0, 1);
        sum0 += __shfl_xor_sync(0xffffffffu, sum0, 2);
        sum1 += __shfl_xor_sync(0xffffffffu, sum1, 1);
        sum1 += __shfl_xor_sync(0xffffffffu, sum1, 2);
        l0 += sum0; l1 += sum1;

        __syncwarp();

        // O += P V
        #pragma unroll
        for (int kc = 0; kc < 8; kc++) {
            unsigned pa[4];
            int col = kc * 8 + tig;
            pa[0] = f2tf32(Ps[sw(qrow0, col)]);
            pa[1] = f2tf32(Ps[sw(qrow1, col)]);
            pa[2] = f2tf32(Ps[sw(qrow0, col + 4)]);
            pa[3] = f2tf32(Ps[sw(qrow1, col + 4)]);
            #pragma unroll
            for (int dn = 0; dn < 8; dn++) {
                unsigned b0 = __float_as_uint(Vs[sw(kc * 8 + tig,     dn * 8 + gid)]);
                unsigned b1 = __float_as_uint(Vs[sw(kc * 8 + tig + 4, dn * 8 + gid)]);
                mma_tf32(o[dn], pa, b0, b1);
            }
        }
        __syncthreads();
    }

    // normalize + write g_att [B,T,C]
    const float inv0 = 1.f / l0;
    const float inv1 = 1.f / l1;
    const int b = bh / NHEAD, h = bh % NHEAD;
    float* base0 = g_att + (size_t)(b * TSEQ + qg0) * CDIM + h * HDIM;
    float* base1 = g_att + (size_t)(b * TSEQ + qg1) * CDIM + h * HDIM;
    #pragma unroll
    for (int dn = 0; dn < 8; dn++) {
        int col = dn * 8 + 2 * tig;
        *(float2*)(base0 + col) = make_float2(o[dn][0] * inv0, o[dn][1] * inv0);
        *(float2*)(base1 + col) = make_float2(o[dn][2] * inv1, o[dn][3] * inv1);
    }
}

// ---------------------------------------------------------------------------
extern "C" void kernel_launch(void* const* d_in, const int* in_sizes, int n_in,
                              void* d_out, int out_size)
{
    const float* x      = (const float*)d_in[0];   // [8,2048,384]
    const float* w_qkv  = (const float*)d_in[1];   // [384,1152]
    const float* w_proj = (const float*)d_in[2];   // [384,384]
    const float* b_proj = (const float*)d_in[3];   // [384]
    float* out = (float*)d_out;                    // [8,2048,384]

    {
        dim3 grid(C3 / 128, MROWS / 128);          // (9, 128)
        gemm_tf32_kernel<C3, false><<<grid, 256>>>(x, w_qkv, nullptr, nullptr);
    }
    {
        dim3 grid(TSEQ / 64, BATCH * NHEAD);       // (32, 48)
        flash_attn_kernel<<<grid, 128>>>();
    }
    {
        dim3 grid(CDIM / 128, MROWS / 128);        // (3, 128)
        gemm_tf32_kernel<CDIM, true><<<grid, 256>>>(nullptr, w_proj, b_proj, out);
    }
}

// round 7
// speedup vs baseline: 3.4451x; 1.0796x over previous
#include <cuda_runtime.h>
#include <cuda_bf16.h>
#include <math_constants.h>
#include <cstdint>

// Problem constants
#define BATCH 8
#define TSEQ  2048
#define NHEAD 6
#define HDIM  64
#define CDIM  (NHEAD * HDIM)      // 384
#define C3    (3 * CDIM)          // 1152
#define MROWS (BATCH * TSEQ)      // 16384

// Scratch (device globals; no runtime allocation allowed)
__device__ float g_q[BATCH * NHEAD * TSEQ * HDIM];   // [B,H,T,D] (tf32-rounded)
__device__ float g_k[BATCH * NHEAD * TSEQ * HDIM];
__device__ float g_v[BATCH * NHEAD * TSEQ * HDIM];
__device__ float g_att[MROWS * CDIM];                // [B,T,C] fp32

// ---------------------------------------------------------------------------
// Common helpers
// ---------------------------------------------------------------------------
__device__ __forceinline__ unsigned f2tf32(float f) {
    unsigned u;
    asm("cvt.rna.tf32.f32 %0, %1;" : "=r"(u) : "f"(f));
    return u;
}
__device__ __forceinline__ float fast_exp2(float x) {
    float y;
    asm("ex2.approx.f32 %0, %1;" : "=f"(y) : "f"(x));
    return y;
}
__device__ __forceinline__ void mma_tf32(float* d, const unsigned* a, unsigned b0, unsigned b1) {
    asm volatile(
        "mma.sync.aligned.m16n8k8.row.col.f32.tf32.tf32.f32 "
        "{%0,%1,%2,%3},{%4,%5,%6,%7},{%8,%9},{%0,%1,%2,%3};"
        : "+f"(d[0]), "+f"(d[1]), "+f"(d[2]), "+f"(d[3])
        : "r"(a[0]), "r"(a[1]), "r"(a[2]), "r"(a[3]), "r"(b0), "r"(b1));
}
__device__ __forceinline__ unsigned smaddr(const void* p) {
    return (unsigned)__cvta_generic_to_shared(p);
}
__device__ __forceinline__ void cp16(unsigned dst, const void* src) {
    asm volatile("cp.async.cg.shared.global [%0], [%1], 16;" :: "r"(dst), "l"(src));
}

// ---------------------------------------------------------------------------
// Single-pass TF32 GEMM (unchanged from round 5)
// ---------------------------------------------------------------------------
#define LDP 136

template<int NC, bool PROJ>
__global__ __launch_bounds__(256, 2) void gemm_tf32_kernel(
    const float* __restrict__ Ain, const float* __restrict__ W,
    const float* __restrict__ bias, float* __restrict__ out)
{
    __shared__ float Ash[16][LDP];
    __shared__ float Bsh[16][LDP];

    const float* A = PROJ ? (const float*)g_att : Ain;

    const int tid  = threadIdx.x;
    const int lane = tid & 31, warp = tid >> 5;
    const int wm = warp >> 1, wn = warp & 1;
    const int gid = lane >> 2, tig = lane & 3;
    const int bm = blockIdx.y * 128, bn = blockIdx.x * 128;

    const int arow  = tid & 127,   acolg = (tid >> 7) * 8;
    const int brow  = tid >> 4,    bcolg = (tid & 15) * 8;

    const float* Aptr = A + (size_t)(bm + arow) * CDIM + acolg;
    const float* Wptr = W + (size_t)brow * NC + bn + bcolg;

    float acc[2][8][4];
    #pragma unroll
    for (int mi = 0; mi < 2; mi++)
        #pragma unroll
        for (int ni = 0; ni < 8; ni++)
            #pragma unroll
            for (int c = 0; c < 4; c++) acc[mi][ni][c] = 0.f;

    float4 va0 = *(const float4*)(Aptr);
    float4 va1 = *(const float4*)(Aptr + 4);
    float4 vb0 = *(const float4*)(Wptr);
    float4 vb1 = *(const float4*)(Wptr + 4);

    #pragma unroll 1
    for (int chunk = 0; chunk < 24; chunk++) {
        {
            const float* a0 = (const float*)&va0;
            const float* a1 = (const float*)&va1;
            #pragma unroll
            for (int j = 0; j < 4; j++) {
                Ash[acolg + j][arow]     = __uint_as_float(f2tf32(a0[j]));
                Ash[acolg + 4 + j][arow] = __uint_as_float(f2tf32(a1[j]));
            }
            float4 r0 = make_float4(__uint_as_float(f2tf32(vb0.x)), __uint_as_float(f2tf32(vb0.y)),
                                    __uint_as_float(f2tf32(vb0.z)), __uint_as_float(f2tf32(vb0.w)));
            float4 r1 = make_float4(__uint_as_float(f2tf32(vb1.x)), __uint_as_float(f2tf32(vb1.y)),
                                    __uint_as_float(f2tf32(vb1.z)), __uint_as_float(f2tf32(vb1.w)));
            *(float4*)&Bsh[brow][bcolg]     = r0;
            *(float4*)&Bsh[brow][bcolg + 4] = r1;
        }
        if (chunk < 23) {
            const float* ap = Aptr + (chunk + 1) * 16;
            const float* wp = Wptr + (size_t)(chunk + 1) * 16 * NC;
            va0 = *(const float4*)(ap);
            va1 = *(const float4*)(ap + 4);
            vb0 = *(const float4*)(wp);
            vb1 = *(const float4*)(wp + 4);
        }
        __syncthreads();

        #pragma unroll
        for (int ks = 0; ks < 2; ks++) {
            const int k0i = ks * 8 + tig;
            const int k1i = k0i + 4;

            unsigned a[2][4];
            #pragma unroll
            for (int mi = 0; mi < 2; mi++) {
                const int m = wm * 32 + mi * 16 + gid;
                a[mi][0] = __float_as_uint(Ash[k0i][m]);
                a[mi][1] = __float_as_uint(Ash[k0i][m + 8]);
                a[mi][2] = __float_as_uint(Ash[k1i][m]);
                a[mi][3] = __float_as_uint(Ash[k1i][m + 8]);
            }
            #pragma unroll
            for (int ni = 0; ni < 8; ni++) {
                const int n = wn * 64 + ni * 8 + gid;
                unsigned b0 = __float_as_uint(Bsh[k0i][n]);
                unsigned b1 = __float_as_uint(Bsh[k1i][n]);
                mma_tf32(acc[0][ni], a[0], b0, b1);
                mma_tf32(acc[1][ni], a[1], b0, b1);
            }
        }
        __syncthreads();
    }

    #pragma unroll
    for (int mi = 0; mi < 2; mi++) {
        const int r0 = bm + wm * 32 + mi * 16 + gid;
        const int r1 = r0 + 8;
        #pragma unroll
        for (int ni = 0; ni < 8; ni++) {
            if (PROJ) {
                const int c = bn + wn * 64 + ni * 8 + tig * 2;
                float bx = bias[c], by = bias[c + 1];
                *(float2*)(out + (size_t)r0 * CDIM + c) =
                    make_float2(acc[mi][ni][0] + bx, acc[mi][ni][1] + by);
                *(float2*)(out + (size_t)r1 * CDIM + c) =
                    make_float2(acc[mi][ni][2] + bx, acc[mi][ni][3] + by);
            } else {
                const int which = bn / CDIM;
                const int cloc  = (bn % CDIM) + wn * 64 + ni * 8 + tig * 2;
                const int h = cloc >> 6, dd = cloc & 63;
                float* dst = (which == 0) ? g_q : (which == 1) ? g_k : g_v;
                const int b0r = r0 >> 11, t0 = r0 & 2047;
                const int b1r = r1 >> 11, t1 = r1 & 2047;
                float2 v0 = make_float2(__uint_as_float(f2tf32(acc[mi][ni][0])),
                                        __uint_as_float(f2tf32(acc[mi][ni][1])));
                float2 v1 = make_float2(__uint_as_float(f2tf32(acc[mi][ni][2])),
                                        __uint_as_float(f2tf32(acc[mi][ni][3])));
                *(float2*)(dst + (((size_t)(b0r * NHEAD + h) * TSEQ + t0) << 6) + dd) = v0;
                *(float2*)(dst + (((size_t)(b1r * NHEAD + h) * TSEQ + t1) << 6) + dd) = v1;
            }
        }
    }
}

// ---------------------------------------------------------------------------
// Causal flash attention, 256 threads (8 warps), Q tile = 128 rows,
// cp.async double-buffered 64-row K/V tiles, tf32 mma.
// Dynamic smem: Kbuf[2][4096] | Vbuf[2][4096] | Ps[128*64]  = 96KB.
// ---------------------------------------------------------------------------
__device__ __forceinline__ int sw(int row, int col) {
    return row * 64 + (((((unsigned)col >> 2) ^ (row & 7)) << 2) | (col & 3));
}

#define SCALE_LOG2E 0.18033688011112042f   // (1/8) * log2(e)

__global__ __launch_bounds__(256, 2) void flash_attn_kernel()
{
    extern __shared__ float smf[];
    float* Kbuf = smf;             // [2][4096]
    float* Vbuf = smf + 8192;      // [2][4096]
    float* Ps   = smf + 16384;     // [128][64] swizzled (Q staging, then P)

    const int bh   = blockIdx.y;
    const int qb   = 15 - blockIdx.x;      // heavy q-blocks scheduled first
    const int tid  = threadIdx.x;
    const int lane = tid & 31;
    const int warp = tid >> 5;
    const int gid  = lane >> 2;
    const int tig  = lane & 3;

    const float* __restrict__ Qb = g_q + (size_t)bh * TSEQ * HDIM;
    const float* __restrict__ Kb = g_k + (size_t)bh * TSEQ * HDIM;
    const float* __restrict__ Vb = g_v + (size_t)bh * TSEQ * HDIM;

    const int qrow0 = warp * 16 + gid;     // 0..127
    const int qrow1 = qrow0 + 8;
    const int qg0   = qb * 128 + qrow0;
    const int qg1   = qb * 128 + qrow1;

    // ---- stage Q tile (128x64) into Ps, swizzled ----
    {
        const float4* Qg = (const float4*)(Qb + (size_t)qb * 128 * HDIM);
        float4* P4 = (float4*)Ps;
        #pragma unroll
        for (int i = 0; i < 8; i++) {
            int idx = i * 256 + tid;       // 0..2047
            int row = idx >> 4, c4 = idx & 15;
            P4[row * 16 + (c4 ^ (row & 7))] = Qg[idx];
        }
    }
    __syncthreads();

    unsigned qa[8][4];
    #pragma unroll
    for (int kc = 0; kc < 8; kc++) {
        int col = kc * 8 + tig;
        qa[kc][0] = __float_as_uint(Ps[sw(qrow0, col)]);
        qa[kc][1] = __float_as_uint(Ps[sw(qrow1, col)]);
        qa[kc][2] = __float_as_uint(Ps[sw(qrow0, col + 4)]);
        qa[kc][3] = __float_as_uint(Ps[sw(qrow1, col + 4)]);
    }
    // each warp reads only its own 16 rows, which only it overwrites with P later

    const int jtmax  = 2 * qb + 1;
    const int mydiag = 2 * qb + (warp >> 2);  // warps 0-3: 2qb, warps 4-7: 2qb+1

    // ---- preload KV tile 0 into buffer 0 ----
    {
        const float4* Kg = (const float4*)Kb;
        const float4* Vg = (const float4*)Vb;
        #pragma unroll
        for (int i = 0; i < 4; i++) {
            int idx = i * 256 + tid;       // 0..1023
            int row = idx >> 4, c4 = idx & 15;
            int s4 = row * 16 + (c4 ^ (row & 7));
            cp16(smaddr(Kbuf + s4 * 4), Kg + idx);
            cp16(smaddr(Vbuf + s4 * 4), Vg + idx);
        }
        asm volatile("cp.async.commit_group;");
    }

    float o[8][4];
    #pragma unroll
    for (int n = 0; n < 8; n++)
        #pragma unroll
        for (int c = 0; c < 4; c++) o[n][c] = 0.f;
    float m0 = -1e30f, m1 = -1e30f, l0 = 0.f, l1 = 0.f;

    #pragma unroll 1
    for (int jt = 0; jt <= jtmax; jt++) {
        const int cur = jt & 1;

        // prefetch next tile into the other buffer (last used at compute jt-1,
        // protected by the trailing __syncthreads of the previous iteration)
        if (jt < jtmax) {
            const float4* Kg = (const float4*)(Kb + (size_t)(jt + 1) * 64 * HDIM);
            const float4* Vg = (const float4*)(Vb + (size_t)(jt + 1) * 64 * HDIM);
            float* Kd = Kbuf + (cur ^ 1) * 4096;
            float* Vd = Vbuf + (cur ^ 1) * 4096;
            #pragma unroll
            for (int i = 0; i < 4; i++) {
                int idx = i * 256 + tid;
                int row = idx >> 4, c4 = idx & 15;
                int s4 = row * 16 + (c4 ^ (row & 7));
                cp16(smaddr(Kd + s4 * 4), Kg + idx);
                cp16(smaddr(Vd + s4 * 4), Vg + idx);
            }
            asm volatile("cp.async.commit_group;");
            asm volatile("cp.async.wait_group 1;");   // current tile complete
        } else {
            asm volatile("cp.async.wait_group 0;");
        }
        __syncthreads();

        if (jt <= mydiag) {
            const float* Ks = Kbuf + cur * 4096;
            const float* Vs = Vbuf + cur * 4096;

            // S = Q K^T (16x64 per warp)
            float s[8][4];
            #pragma unroll
            for (int n = 0; n < 8; n++) {
                s[n][0] = s[n][1] = s[n][2] = s[n][3] = 0.f;
                #pragma unroll
                for (int kc = 0; kc < 8; kc++) {
                    unsigned b0 = __float_as_uint(Ks[sw(n * 8 + gid, kc * 8 + tig)]);
                    unsigned b1 = __float_as_uint(Ks[sw(n * 8 + gid, kc * 8 + tig + 4)]);
                    mma_tf32(s[n], qa[kc], b0, b1);
                }
            }

            // scale + causal mask (only on this warp's diagonal tile)
            const int jbase = jt * 64;
            const bool diag = (jt == mydiag);
            #pragma unroll
            for (int n = 0; n < 8; n++) {
                #pragma unroll
                for (int c = 0; c < 4; c++) s[n][c] *= SCALE_LOG2E;
                if (diag) {
                    int j0 = jbase + n * 8 + 2 * tig;
                    if (j0 > qg0)     s[n][0] = -1e30f;
                    if (j0 + 1 > qg0) s[n][1] = -1e30f;
                    if (j0 > qg1)     s[n][2] = -1e30f;
                    if (j0 + 1 > qg1) s[n][3] = -1e30f;
                }
            }

            // row max (quad reduce)
            float mx0 = -1e30f, mx1 = -1e30f;
            #pragma unroll
            for (int n = 0; n < 8; n++) {
                mx0 = fmaxf(mx0, fmaxf(s[n][0], s[n][1]));
                mx1 = fmaxf(mx1, fmaxf(s[n][2], s[n][3]));
            }
            mx0 = fmaxf(mx0, __shfl_xor_sync(0xffffffffu, mx0, 1));
            mx0 = fmaxf(mx0, __shfl_xor_sync(0xffffffffu, mx0, 2));
            mx1 = fmaxf(mx1, __shfl_xor_sync(0xffffffffu, mx1, 1));
            mx1 = fmaxf(mx1, __shfl_xor_sync(0xffffffffu, mx1, 2));

            const float mn0 = fmaxf(m0, mx0);
            const float mn1 = fmaxf(m1, mx1);
            const float cr0 = fast_exp2(m0 - mn0);
            const float cr1 = fast_exp2(m1 - mn1);
            m0 = mn0; m1 = mn1;
            l0 *= cr0; l1 *= cr1;
            #pragma unroll
            for (int n = 0; n < 8; n++) {
                o[n][0] *= cr0; o[n][1] *= cr0;
                o[n][2] *= cr1; o[n][3] *= cr1;
            }

            // p = exp2(s - m); accumulate l; store P (own rows only)
            float sum0 = 0.f, sum1 = 0.f;
            #pragma unroll
            for (int n = 0; n < 8; n++) {
                float p00 = fast_exp2(s[n][0] - mn0);
                float p01 = fast_exp2(s[n][1] - mn0);
                float p10 = fast_exp2(s[n][2] - mn1);
                float p11 = fast_exp2(s[n][3] - mn1);
                sum0 += p00 + p01;
                sum1 += p10 + p11;
                int col = n * 8 + 2 * tig;
                *(float2*)&Ps[sw(qrow0, col)] = make_float2(p00, p01);
                *(float2*)&Ps[sw(qrow1, col)] = make_float2(p10, p11);
            }
            sum0 += __shfl_xor_sync(0xffffffffu, sum0, 1);
            sum0 += __shfl_xor_sync(0xffffffffu, sum0, 2);
            sum1 += __shfl_xor_sync(0xffffffffu, sum1, 1);
            sum1 += __shfl_xor_sync(0xffffffffu, sum1, 2);
            l0 += sum0; l1 += sum1;

            __syncwarp();

            // O += P V (16x64 per warp)
            #pragma unroll
            for (int kc = 0; kc < 8; kc++) {
                unsigned pa[4];
                int col = kc * 8 + tig;
                pa[0] = f2tf32(Ps[sw(qrow0, col)]);
                pa[1] = f2tf32(Ps[sw(qrow1, col)]);
                pa[2] = f2tf32(Ps[sw(qrow0, col + 4)]);
                pa[3] = f2tf32(Ps[sw(qrow1, col + 4)]);
                #pragma unroll
                for (int dn = 0; dn < 8; dn++) {
                    unsigned b0 = __float_as_uint(Vs[sw(kc * 8 + tig,     dn * 8 + gid)]);
                    unsigned b1 = __float_as_uint(Vs[sw(kc * 8 + tig + 4, dn * 8 + gid)]);
                    mma_tf32(o[dn], pa, b0, b1);
                }
            }
        }
        __syncthreads();   // K/V consumption complete before next prefetch overwrites
    }

    // ---- normalize and write to g_att [B,T,C] ----
    const float inv0 = 1.f / l0;
    const float inv1 = 1.f / l1;
    const int b = bh / NHEAD, h = bh % NHEAD;
    float* base0 = g_att + (size_t)(b * TSEQ + qg0) * CDIM + h * HDIM;
    float* base1 = g_att + (size_t)(b * TSEQ + qg1) * CDIM + h * HDIM;
    #pragma unroll
    for (int dn = 0; dn < 8; dn++) {
        int col = dn * 8 + 2 * tig;
        *(float2*)(base0 + col) = make_float2(o[dn][0] * inv0, o[dn][1] * inv0);
        *(float2*)(base1 + col) = make_float2(o[dn][2] * inv1, o[dn][3] * inv1);
    }
}

// ---------------------------------------------------------------------------
extern "C" void kernel_launch(void* const* d_in, const int* in_sizes, int n_in,
                              void* d_out, int out_size)
{
    const float* x      = (const float*)d_in[0];   // [8,2048,384]
    const float* w_qkv  = (const float*)d_in[1];   // [384,1152]
    const float* w_proj = (const float*)d_in[2];   // [384,384]
    const float* b_proj = (const float*)d_in[3];   // [384]
    float* out = (float*)d_out;                    // [8,2048,384]

    {
        dim3 grid(C3 / 128, MROWS / 128);          // (9, 128)
        gemm_tf32_kernel<C3, false><<<grid, 256>>>(x, w_qkv, nullptr, nullptr);
    }
    {
        cudaFuncSetAttribute(flash_attn_kernel,
                             cudaFuncAttributeMaxDynamicSharedMemorySize, 98304);
        dim3 grid(TSEQ / 128, BATCH * NHEAD);      // (16, 48)
        flash_attn_kernel<<<grid, 256, 98304>>>();
    }
    {
        dim3 grid(CDIM / 128, MROWS / 128);        // (3, 128)
        gemm_tf32_kernel<CDIM, true><<<grid, 256>>>(nullptr, w_proj, b_proj, out);
    }
}

// round 8
// speedup vs baseline: 3.4812x; 1.0105x over previous
#include <cuda_runtime.h>
#include <cuda_bf16.h>
#include <math_constants.h>
#include <cstdint>

// Problem constants
#define BATCH 8
#define TSEQ  2048
#define NHEAD 6
#define HDIM  64
#define CDIM  (NHEAD * HDIM)      // 384
#define C3    (3 * CDIM)          // 1152
#define MROWS (BATCH * TSEQ)      // 16384

#define SCALE_LOG2E 0.18033688011112042f   // (1/8) * log2(e), folded into q

// Scratch (device globals; no runtime allocation allowed)
__device__ float g_q[BATCH * NHEAD * TSEQ * HDIM];   // [B,H,T,D] tf32, pre-scaled
__device__ float g_k[BATCH * NHEAD * TSEQ * HDIM];
__device__ float g_v[BATCH * NHEAD * TSEQ * HDIM];
__device__ float g_att[MROWS * CDIM];                // [B,T,C] fp32

// ---------------------------------------------------------------------------
// Common helpers
// ---------------------------------------------------------------------------
__device__ __forceinline__ unsigned f2tf32(float f) {
    unsigned u;
    asm("cvt.rna.tf32.f32 %0, %1;" : "=r"(u) : "f"(f));
    return u;
}
__device__ __forceinline__ float fast_exp2(float x) {
    float y;
    asm("ex2.approx.f32 %0, %1;" : "=f"(y) : "f"(x));
    return y;
}
__device__ __forceinline__ void mma_tf32(float* d, const unsigned* a, unsigned b0, unsigned b1) {
    asm volatile(
        "mma.sync.aligned.m16n8k8.row.col.f32.tf32.tf32.f32 "
        "{%0,%1,%2,%3},{%4,%5,%6,%7},{%8,%9},{%0,%1,%2,%3};"
        : "+f"(d[0]), "+f"(d[1]), "+f"(d[2]), "+f"(d[3])
        : "r"(a[0]), "r"(a[1]), "r"(a[2]), "r"(a[3]), "r"(b0), "r"(b1));
}
__device__ __forceinline__ unsigned smaddr(const void* p) {
    return (unsigned)__cvta_generic_to_shared(p);
}
__device__ __forceinline__ void cp16(unsigned dst, const void* src) {
    asm volatile("cp.async.cg.shared.global [%0], [%1], 16;" :: "r"(dst), "l"(src));
}

// ---------------------------------------------------------------------------
// Single-pass TF32 GEMM, double-buffered smem, ONE sync per BK=16 chunk.
// BM=BN=128, 256 threads = 8 warps (4m x 2n), warp tile 32x64.
// PROJ=false: A = x, scatter into g_q (pre-scaled by SCALE_LOG2E)/g_k/g_v.
// PROJ=true : A = g_att (resolved in kernel), add bias -> out.
// ---------------------------------------------------------------------------
#define LDP 136

template<int NC, bool PROJ>
__global__ __launch_bounds__(256, 2) void gemm_tf32_kernel(
    const float* __restrict__ Ain, const float* __restrict__ W,
    const float* __restrict__ bias, float* __restrict__ out)
{
    __shared__ float Ash[2][16][LDP];
    __shared__ float Bsh[2][16][LDP];

    const float* A = PROJ ? (const float*)g_att : Ain;

    const int tid  = threadIdx.x;
    const int lane = tid & 31, warp = tid >> 5;
    const int wm = warp >> 1, wn = warp & 1;
    const int gid = lane >> 2, tig = lane & 3;
    const int bm = blockIdx.y * 128, bn = blockIdx.x * 128;

    const int arow  = tid & 127,   acolg = (tid >> 7) * 8;
    const int brow  = tid >> 4,    bcolg = (tid & 15) * 8;

    const float* Aptr = A + (size_t)(bm + arow) * CDIM + acolg;
    const float* Wptr = W + (size_t)brow * NC + bn + bcolg;

    float acc[2][8][4];
    #pragma unroll
    for (int mi = 0; mi < 2; mi++)
        #pragma unroll
        for (int ni = 0; ni < 8; ni++)
            #pragma unroll
            for (int c = 0; c < 4; c++) acc[mi][ni][c] = 0.f;

    float4 va0, va1, vb0, vb1;

#define LOAD_CHUNK(c)  do { \
        const float* ap = Aptr + (c) * 16; \
        const float* wp = Wptr + (size_t)(c) * 16 * NC; \
        va0 = *(const float4*)(ap); \
        va1 = *(const float4*)(ap + 4); \
        vb0 = *(const float4*)(wp); \
        vb1 = *(const float4*)(wp + 4); \
    } while (0)

#define STAGE(BUF)  do { \
        const float* a0 = (const float*)&va0; \
        const float* a1 = (const float*)&va1; \
        _Pragma("unroll") \
        for (int j = 0; j < 4; j++) { \
            Ash[BUF][acolg + j][arow]     = __uint_as_float(f2tf32(a0[j])); \
            Ash[BUF][acolg + 4 + j][arow] = __uint_as_float(f2tf32(a1[j])); \
        } \
        float4 r0 = make_float4(__uint_as_float(f2tf32(vb0.x)), __uint_as_float(f2tf32(vb0.y)), \
                                __uint_as_float(f2tf32(vb0.z)), __uint_as_float(f2tf32(vb0.w))); \
        float4 r1 = make_float4(__uint_as_float(f2tf32(vb1.x)), __uint_as_float(f2tf32(vb1.y)), \
                                __uint_as_float(f2tf32(vb1.z)), __uint_as_float(f2tf32(vb1.w))); \
        *(float4*)&Bsh[BUF][brow][bcolg]     = r0; \
        *(float4*)&Bsh[BUF][brow][bcolg + 4] = r1; \
    } while (0)

    LOAD_CHUNK(0);
    STAGE(0);
    LOAD_CHUNK(1);
    __syncthreads();

    #pragma unroll 1
    for (int c = 0; c < 24; c++) {
        const int cur = c & 1;
        if (c < 23) STAGE(cur ^ 1);           // stage chunk c+1 (regs -> other buf)
        if (c < 22) LOAD_CHUNK(c + 2);        // prefetch chunk c+2 into regs

        #pragma unroll
        for (int ks = 0; ks < 2; ks++) {
            const int k0i = ks * 8 + tig;
            const int k1i = k0i + 4;

            unsigned a[2][4];
            #pragma unroll
            for (int mi = 0; mi < 2; mi++) {
                const int m = wm * 32 + mi * 16 + gid;
                a[mi][0] = __float_as_uint(Ash[cur][k0i][m]);
                a[mi][1] = __float_as_uint(Ash[cur][k0i][m + 8]);
                a[mi][2] = __float_as_uint(Ash[cur][k1i][m]);
                a[mi][3] = __float_as_uint(Ash[cur][k1i][m + 8]);
            }
            #pragma unroll
            for (int ni = 0; ni < 8; ni++) {
                const int n = wn * 64 + ni * 8 + gid;
                unsigned b0 = __float_as_uint(Bsh[cur][k0i][n]);
                unsigned b1 = __float_as_uint(Bsh[cur][k1i][n]);
                mma_tf32(acc[0][ni], a[0], b0, b1);
                mma_tf32(acc[1][ni], a[1], b0, b1);
            }
        }
        __syncthreads();
    }

#undef LOAD_CHUNK
#undef STAGE

    // ---- epilogue ----
    #pragma unroll
    for (int mi = 0; mi < 2; mi++) {
        const int r0 = bm + wm * 32 + mi * 16 + gid;
        const int r1 = r0 + 8;
        #pragma unroll
        for (int ni = 0; ni < 8; ni++) {
            if (PROJ) {
                const int c = bn + wn * 64 + ni * 8 + tig * 2;
                float bx = bias[c], by = bias[c + 1];
                *(float2*)(out + (size_t)r0 * CDIM + c) =
                    make_float2(acc[mi][ni][0] + bx, acc[mi][ni][1] + by);
                *(float2*)(out + (size_t)r1 * CDIM + c) =
                    make_float2(acc[mi][ni][2] + bx, acc[mi][ni][3] + by);
            } else {
                const int which = bn / CDIM;                       // 0=q,1=k,2=v
                const int cloc  = (bn % CDIM) + wn * 64 + ni * 8 + tig * 2;
                const int h = cloc >> 6, dd = cloc & 63;
                float* dst = (which == 0) ? g_q : (which == 1) ? g_k : g_v;
                const float sc = (which == 0) ? SCALE_LOG2E : 1.0f;  // fold softmax scale into q
                const int b0r = r0 >> 11, t0 = r0 & 2047;
                const int b1r = r1 >> 11, t1 = r1 & 2047;
                float2 v0 = make_float2(__uint_as_float(f2tf32(acc[mi][ni][0] * sc)),
                                        __uint_as_float(f2tf32(acc[mi][ni][1] * sc)));
                float2 v1 = make_float2(__uint_as_float(f2tf32(acc[mi][ni][2] * sc)),
                                        __uint_as_float(f2tf32(acc[mi][ni][3] * sc)));
                *(float2*)(dst + (((size_t)(b0r * NHEAD + h) * TSEQ + t0) << 6) + dd) = v0;
                *(float2*)(dst + (((size_t)(b1r * NHEAD + h) * TSEQ + t1) << 6) + dd) = v1;
            }
        }
    }
}

// ---------------------------------------------------------------------------
// Causal flash attention, 256 threads (8 warps), Q tile = 128 rows,
// cp.async double-buffered K/V, ONE __syncthreads per KV tile.
// q is pre-scaled by (1/8)*log2(e) at the qkv epilogue.
// Dynamic smem: Kbuf[2][4096] | Vbuf[2][4096] | Ps[128*64] = 96KB.
// ---------------------------------------------------------------------------
__device__ __forceinline__ int sw(int row, int col) {
    return row * 64 + (((((unsigned)col >> 2) ^ (row & 7)) << 2) | (col & 3));
}

__global__ __launch_bounds__(256, 2) void flash_attn_kernel()
{
    extern __shared__ float smf[];
    float* Kbuf = smf;             // [2][4096]
    float* Vbuf = smf + 8192;      // [2][4096]
    float* Ps   = smf + 16384;     // [128][64] swizzled (Q staging, then P)

    const int bh   = blockIdx.y;
    const int qb   = 15 - blockIdx.x;      // heavy q-blocks scheduled first
    const int tid  = threadIdx.x;
    const int lane = tid & 31;
    const int warp = tid >> 5;
    const int gid  = lane >> 2;
    const int tig  = lane & 3;

    const float* __restrict__ Qb = g_q + (size_t)bh * TSEQ * HDIM;
    const float* __restrict__ Kb = g_k + (size_t)bh * TSEQ * HDIM;
    const float* __restrict__ Vb = g_v + (size_t)bh * TSEQ * HDIM;

    const int qrow0 = warp * 16 + gid;     // 0..127
    const int qrow1 = qrow0 + 8;
    const int qg0   = qb * 128 + qrow0;
    const int qg1   = qb * 128 + qrow1;

    // ---- stage Q tile (128x64) into Ps, swizzled ----
    {
        const float4* Qg = (const float4*)(Qb + (size_t)qb * 128 * HDIM);
        float4* P4 = (float4*)Ps;
        #pragma unroll
        for (int i = 0; i < 8; i++) {
            int idx = i * 256 + tid;       // 0..2047
            int row = idx >> 4, c4 = idx & 15;
            P4[row * 16 + (c4 ^ (row & 7))] = Qg[idx];
        }
    }

    // ---- preload KV tile 0 into buffer 0 ----
    {
        const float4* Kg = (const float4*)Kb;
        const float4* Vg = (const float4*)Vb;
        #pragma unroll
        for (int i = 0; i < 4; i++) {
            int idx = i * 256 + tid;       // 0..1023
            int row = idx >> 4, c4 = idx & 15;
            int s4 = row * 16 + (c4 ^ (row & 7));
            cp16(smaddr(Kbuf + s4 * 4), Kg + idx);
            cp16(smaddr(Vbuf + s4 * 4), Vg + idx);
        }
        asm volatile("cp.async.commit_group;");
    }
    __syncthreads();   // Q staging visible

    unsigned qa[8][4];
    #pragma unroll
    for (int kc = 0; kc < 8; kc++) {
        int col = kc * 8 + tig;
        qa[kc][0] = __float_as_uint(Ps[sw(qrow0, col)]);
        qa[kc][1] = __float_as_uint(Ps[sw(qrow1, col)]);
        qa[kc][2] = __float_as_uint(Ps[sw(qrow0, col + 4)]);
        qa[kc][3] = __float_as_uint(Ps[sw(qrow1, col + 4)]);
    }
    // each warp reads only its own 16 rows, which only it overwrites with P later

    const int jtmax  = 2 * qb + 1;
    const int mydiag = 2 * qb + (warp >> 2);  // warps 0-3: 2qb, warps 4-7: 2qb+1

    float o[8][4];
    #pragma unroll
    for (int n = 0; n < 8; n++)
        #pragma unroll
        for (int c = 0; c < 4; c++) o[n][c] = 0.f;
    float m0 = -1e30f, m1 = -1e30f, l0 = 0.f, l1 = 0.f;

    #pragma unroll 1
    for (int jt = 0; jt <= jtmax; jt++) {
        const int cur = jt & 1;

        asm volatile("cp.async.wait_group 0;");   // tile jt landed
        __syncthreads();                          // visible to all; buf[cur^1] free

        // issue prefetch of tile jt+1 into the other buffer (overlaps compute)
        if (jt < jtmax) {
            const float4* Kg = (const float4*)(Kb + (size_t)(jt + 1) * 64 * HDIM);
            const float4* Vg = (const float4*)(Vb + (size_t)(jt + 1) * 64 * HDIM);
            float* Kd = Kbuf + (cur ^ 1) * 4096;
            float* Vd = Vbuf + (cur ^ 1) * 4096;
            #pragma unroll
            for (int i = 0; i < 4; i++) {
                int idx = i * 256 + tid;
                int row = idx >> 4, c4 = idx & 15;
                int s4 = row * 16 + (c4 ^ (row & 7));
                cp16(smaddr(Kd + s4 * 4), Kg + idx);
                cp16(smaddr(Vd + s4 * 4), Vg + idx);
            }
            asm volatile("cp.async.commit_group;");
        }

        if (jt <= mydiag) {
            const float* Ks = Kbuf + cur * 4096;
            const float* Vs = Vbuf + cur * 4096;

            // S = Q K^T (16x64 per warp); q pre-scaled, so S is already log2-scaled
            float s[8][4];
            #pragma unroll
            for (int n = 0; n < 8; n++) {
                s[n][0] = s[n][1] = s[n][2] = s[n][3] = 0.f;
                #pragma unroll
                for (int kc = 0; kc < 8; kc++) {
                    unsigned b0 = __float_as_uint(Ks[sw(n * 8 + gid, kc * 8 + tig)]);
                    unsigned b1 = __float_as_uint(Ks[sw(n * 8 + gid, kc * 8 + tig + 4)]);
                    mma_tf32(s[n], qa[kc], b0, b1);
                }
            }

            // causal mask (diagonal tile only)
            if (jt == mydiag) {
                const int jbase = jt * 64;
                #pragma unroll
                for (int n = 0; n < 8; n++) {
                    int j0 = jbase + n * 8 + 2 * tig;
                    if (j0 > qg0)     s[n][0] = -1e30f;
                    if (j0 + 1 > qg0) s[n][1] = -1e30f;
                    if (j0 > qg1)     s[n][2] = -1e30f;
                    if (j0 + 1 > qg1) s[n][3] = -1e30f;
                }
            }

            // row max (quad reduce)
            float mx0 = -1e30f, mx1 = -1e30f;
            #pragma unroll
            for (int n = 0; n < 8; n++) {
                mx0 = fmaxf(mx0, fmaxf(s[n][0], s[n][1]));
                mx1 = fmaxf(mx1, fmaxf(s[n][2], s[n][3]));
            }
            mx0 = fmaxf(mx0, __shfl_xor_sync(0xffffffffu, mx0, 1));
            mx0 = fmaxf(mx0, __shfl_xor_sync(0xffffffffu, mx0, 2));
            mx1 = fmaxf(mx1, __shfl_xor_sync(0xffffffffu, mx1, 1));
            mx1 = fmaxf(mx1, __shfl_xor_sync(0xffffffffu, mx1, 2));

            const float mn0 = fmaxf(m0, mx0);
            const float mn1 = fmaxf(m1, mx1);
            const float cr0 = fast_exp2(m0 - mn0);
            const float cr1 = fast_exp2(m1 - mn1);
            m0 = mn0; m1 = mn1;
            l0 *= cr0; l1 *= cr1;
            #pragma unroll
            for (int n = 0; n < 8; n++) {
                o[n][0] *= cr0; o[n][1] *= cr0;
                o[n][2] *= cr1; o[n][3] *= cr1;
            }

            // p = exp2(s - m); accumulate l; store P (own rows only)
            float sum0 = 0.f, sum1 = 0.f;
            #pragma unroll
            for (int n = 0; n < 8; n++) {
                float p00 = fast_exp2(s[n][0] - mn0);
                float p01 = fast_exp2(s[n][1] - mn0);
                float p10 = fast_exp2(s[n][2] - mn1);
                float p11 = fast_exp2(s[n][3] - mn1);
                sum0 += p00 + p01;
                sum1 += p10 + p11;
                int col = n * 8 + 2 * tig;
                *(float2*)&Ps[sw(qrow0, col)] = make_float2(p00, p01);
                *(float2*)&Ps[sw(qrow1, col)] = make_float2(p10, p11);
            }
            sum0 += __shfl_xor_sync(0xffffffffu, sum0, 1);
            sum0 += __shfl_xor_sync(0xffffffffu, sum0, 2);
            sum1 += __shfl_xor_sync(0xffffffffu, sum1, 1);
            sum1 += __shfl_xor_sync(0xffffffffu, sum1, 2);
            l0 += sum0; l1 += sum1;

            __syncwarp();

            // O += P V (16x64 per warp)
            #pragma unroll
            for (int kc = 0; kc < 8; kc++) {
                unsigned pa[4];
                int col = kc * 8 + tig;
                pa[0] = f2tf32(Ps[sw(qrow0, col)]);
                pa[1] = f2tf32(Ps[sw(qrow1, col)]);
                pa[2] = f2tf32(Ps[sw(qrow0, col + 4)]);
                pa[3] = f2tf32(Ps[sw(qrow1, col + 4)]);
                #pragma unroll
                for (int dn = 0; dn < 8; dn++) {
                    unsigned b0 = __float_as_uint(Vs[sw(kc * 8 + tig,     dn * 8 + gid)]);
                    unsigned b1 = __float_as_uint(Vs[sw(kc * 8 + tig + 4, dn * 8 + gid)]);
                    mma_tf32(o[dn], pa, b0, b1);
                }
            }
        }
        // no trailing barrier: next iteration's wait+sync provides the fence
    }

    // ---- normalize and write to g_att [B,T,C] ----
    const float inv0 = 1.f / l0;
    const float inv1 = 1.f / l1;
    const int b = bh / NHEAD, h = bh % NHEAD;
    float* base0 = g_att + (size_t)(b * TSEQ + qg0) * CDIM + h * HDIM;
    float* base1 = g_att + (size_t)(b * TSEQ + qg1) * CDIM + h * HDIM;
    #pragma unroll
    for (int dn = 0; dn < 8; dn++) {
        int col = dn * 8 + 2 * tig;
        *(float2*)(base0 + col) = make_float2(o[dn][0] * inv0, o[dn][1] * inv0);
        *(float2*)(base1 + col) = make_float2(o[dn][2] * inv1, o[dn][3] * inv1);
    }
}

// ---------------------------------------------------------------------------
extern "C" void kernel_launch(void* const* d_in, const int* in_sizes, int n_in,
                              void* d_out, int out_size)
{
    const float* x      = (const float*)d_in[0];   // [8,2048,384]
    const float* w_qkv  = (const float*)d_in[1];   // [384,1152]
    const float* w_proj = (const float*)d_in[2];   // [384,384]
    const float* b_proj = (const float*)d_in[3];   // [384]
    float* out = (float*)d_out;                    // [8,2048,384]

    {
        dim3 grid(C3 / 128, MROWS / 128);          // (9, 128)
        gemm_tf32_kernel<C3, false><<<grid, 256>>>(x, w_qkv, nullptr, nullptr);
    }
    {
        cudaFuncSetAttribute(flash_attn_kernel,
                             cudaFuncAttributeMaxDynamicSharedMemorySize, 98304);
        dim3 grid(TSEQ / 128, BATCH * NHEAD);      // (16, 48)
        flash_attn_kernel<<<grid, 256, 98304>>>();
    }
    {
        dim3 grid(CDIM / 128, MROWS / 128);        // (3, 128)
        gemm_tf32_kernel<CDIM, true><<<grid, 256>>>(nullptr, w_proj, b_proj, out);
    }
}